// round 7
// baseline (speedup 1.0000x reference)
#include <cuda_runtime.h>
#include <math.h>
#include <stdint.h>

// Problem constants (B=4, S=2048, H=128, NH=8)
#define HB 4
#define SEQ 2048
#define HD 128
#define NH 8
#define HEADS (HB * NH)            // 32
#define HEADELEMS (SEQ * HD)       // 262144
#define YELEMS (HB * SEQ * NH * HD) // 8388608

// Scratch (device globals: allocation-free per harness rules)
__device__ float g_q[YELEMS];
__device__ float g_k[YELEMS];
__device__ float g_v[YELEMS];
__device__ float g_o[YELEMS];

__device__ __forceinline__ uint32_t f2tf(float f) {
    uint32_t u;
    asm("cvt.rna.tf32.f32 %0, %1;" : "=r"(u) : "f"(f));
    return u;
}

__device__ __forceinline__ void mma_tf32(float c[4],
    uint32_t a0, uint32_t a1, uint32_t a2, uint32_t a3,
    uint32_t b0, uint32_t b1)
{
    asm volatile(
        "mma.sync.aligned.m16n8k8.row.col.f32.tf32.tf32.f32 "
        "{%0,%1,%2,%3}, {%4,%5,%6,%7}, {%8,%9}, {%0,%1,%2,%3};\n"
        : "+f"(c[0]), "+f"(c[1]), "+f"(c[2]), "+f"(c[3])
        : "r"(a0), "r"(a1), "r"(a2), "r"(a3), "r"(b0), "r"(b1));
}

// ---------------------------------------------------------------------------
// TF32 tensor-core GEMM. BN=64 (NT=8) instantiations + launch_bounds(256,2)
// give smem 104KB/CTA and regs<=128 -> 2 CTAs/SM.
// ---------------------------------------------------------------------------
template<int BN, int NKITER>
__global__ __launch_bounds__(256, 2)
void tf32_gemm_kernel(const float* __restrict__ A, int lda,
                      const float* __restrict__ B, int ldb,
                      float* __restrict__ C0, float* __restrict__ C1,
                      float* __restrict__ C2, int ldc, int segW)
{
    constexpr int BM = 128;
    constexpr int BK = 128;
    constexpr int LDA_S = 132;
    constexpr int LDB_S = BN + 8;
    constexpr int NT = BN / 8;

    extern __shared__ uint32_t smg[];
    uint32_t* As = smg;
    uint32_t* Bs = smg + BM * LDA_S;

    const int tid  = threadIdx.x;
    const int w    = tid >> 5;
    const int lane = tid & 31;
    const int g    = lane >> 2;
    const int c4   = lane & 3;
    const int mw   = w * 16;

    const int row0 = blockIdx.y * BM;
    const int colg = blockIdx.x * BN;
    const int seg  = colg / segW;
    float* C = (seg == 0) ? C0 : ((seg == 1) ? C1 : C2);
    const int coll = colg - seg * segW;

    float acc[NT][4];
    #pragma unroll
    for (int t = 0; t < NT; t++)
        #pragma unroll
        for (int j = 0; j < 4; j++) acc[t][j] = 0.0f;

    for (int kt = 0; kt < NKITER; kt++) {
        const int k0 = kt * BK;

        #pragma unroll
        for (int p = 0; p < (BM * BK) / (256 * 4); p++) {
            int idx = p * 256 + tid;
            int r = idx >> 5;
            int c = (idx & 31) * 4;
            float4 t = *(const float4*)&A[(long)(row0 + r) * lda + k0 + c];
            *(uint4*)&As[r * LDA_S + c] =
                make_uint4(f2tf(t.x), f2tf(t.y), f2tf(t.z), f2tf(t.w));
        }
        #pragma unroll
        for (int p = 0; p < (BK * BN) / (256 * 4); p++) {
            int idx = p * 256 + tid;
            int r = idx / (BN / 4);
            int c = (idx % (BN / 4)) * 4;
            float4 t = *(const float4*)&B[(long)(k0 + r) * ldb + colg + c];
            *(uint4*)&Bs[r * LDB_S + c] =
                make_uint4(f2tf(t.x), f2tf(t.y), f2tf(t.z), f2tf(t.w));
        }
        __syncthreads();

        #pragma unroll
        for (int kcix = 0; kcix < BK / 8; kcix++) {
            const int kc = kcix * 8;
            uint32_t a0 = As[(mw + g)     * LDA_S + kc + c4];
            uint32_t a1 = As[(mw + g + 8) * LDA_S + kc + c4];
            uint32_t a2 = As[(mw + g)     * LDA_S + kc + 4 + c4];
            uint32_t a3 = As[(mw + g + 8) * LDA_S + kc + 4 + c4];
            #pragma unroll
            for (int t = 0; t < NT; t++) {
                uint32_t b0 = Bs[(kc + c4)     * LDB_S + t * 8 + g];
                uint32_t b1 = Bs[(kc + 4 + c4) * LDB_S + t * 8 + g];
                mma_tf32(acc[t], a0, a1, a2, a3, b0, b1);
            }
        }
        __syncthreads();
    }

    const int r0 = row0 + mw + g;
    const int r1 = r0 + 8;
    #pragma unroll
    for (int t = 0; t < NT; t++) {
        const int col = coll + t * 8 + c4 * 2;
        *(float2*)&C[(long)r0 * ldc + col] = make_float2(acc[t][0], acc[t][1]);
        *(float2*)&C[(long)r1 * ldc + col] = make_float2(acc[t][2], acc[t][3]);
    }
}

// ---------------------------------------------------------------------------
// TF32 flash attention v3: BQ=64, 128 threads, 2 CTAs/SM.
// Q fragments live in REGISTERS (staged once through the K buffer):
// mainloop smem traffic is K-fragments, P store/load, V-fragments only.
// Pair-interleaved layouts (round-6, validated): all fragment loads LDS.64.
// smem/CTA = 87,040 B -> 2 CTAs/SM; launch_bounds(128,2).
// ---------------------------------------------------------------------------
#define BQ 64
#define BKV 64
#define LDK 136
#define LDVP 264
#define LDP 72

#define KS_OFF 0
#define VP_OFF (BKV * LDK)                  // 8704
#define PS_OFF (VP_OFF + 32 * LDVP)         // 17152
#define SMEM_WORDS (PS_OFF + BQ * LDP)      // 21760 words = 87040 B

__global__ __launch_bounds__(128, 2)
void flash_tf32_kernel(const float* __restrict__ gq, const float* __restrict__ gk,
                       const float* __restrict__ gv, float* __restrict__ go)
{
    extern __shared__ uint32_t sm[];
    uint32_t* Ks = sm + KS_OFF;
    uint32_t* Vp = sm + VP_OFF;
    uint32_t* Ps = sm + PS_OFF;

    const int tid  = threadIdx.x;
    const int lane = tid & 31;
    const int g    = lane >> 2;
    const int c4   = lane & 3;
    const int mw   = (tid >> 5) * 16;       // warp row base (4 warps x 16 = 64)

    const int hb = blockIdx.x;
    const int qt = (int)gridDim.y - 1 - (int)blockIdx.y;  // big q-tiles first
    const int q0 = qt * BQ;

    const float* Q = gq + (long)hb * HEADELEMS;
    const float* K = gk + (long)hb * HEADELEMS;
    const float* V = gv + (long)hb * HEADELEMS;
    float*       O = go + (long)hb * HEADELEMS;

    const float scale = 0.08838834764831845f;  // 1/sqrt(128)

    // ---- stage Q (pre-scaled, pair layout) through the Ks buffer ----
    #pragma unroll
    for (int t8 = 0; t8 < 8; t8++) {
        int cid = t8 * 128 + tid;           // 64 rows x 16 chunks
        int r = cid >> 4, ch = cid & 15;
        const float* src = &Q[(q0 + r) * HD + ch * 8];
        float4 a = *(const float4*)src;
        float4 b = *(const float4*)(src + 4);
        uint32_t* dst = &Ks[r * LDK + ch * 8];
        *(uint4*)dst = make_uint4(f2tf(a.x * scale), f2tf(b.x * scale),
                                  f2tf(a.y * scale), f2tf(b.y * scale));
        *(uint4*)(dst + 4) = make_uint4(f2tf(a.z * scale), f2tf(b.z * scale),
                                        f2tf(a.w * scale), f2tf(b.w * scale));
    }
    __syncthreads();

    // ---- hoist Q fragments to registers: qf0/qf1[k] = (a0,a2)/(a1,a3) ----
    uint2 qf0[16], qf1[16];
    #pragma unroll
    for (int k = 0; k < 16; k++) {
        qf0[k] = *(const uint2*)&Ks[(mw + g)     * LDK + k * 8 + 2 * c4];
        qf1[k] = *(const uint2*)&Ks[(mw + g + 8) * LDK + k * 8 + 2 * c4];
    }
    __syncthreads();

    float of[16][4];
    #pragma unroll
    for (int t = 0; t < 16; t++)
        #pragma unroll
        for (int j = 0; j < 4; j++) of[t][j] = 0.0f;
    float m0 = -INFINITY, m1 = -INFINITY, l0 = 0.0f, l1 = 0.0f;

    const int poslo = ((c4 & 1) << 2) | (c4 >> 1);   // P pair position for col 2*c4
    const int nkv = qt + 1;

    for (int kt = 0; kt < nkv; kt++) {
        const int k0 = kt * BKV;

        // ---- load K tile (pair layout) ----
        #pragma unroll
        for (int t8 = 0; t8 < 8; t8++) {
            int cid = t8 * 128 + tid;
            int r = cid >> 4, ch = cid & 15;
            const float* src = &K[(k0 + r) * HD + ch * 8];
            float4 a = *(const float4*)src;
            float4 b = *(const float4*)(src + 4);
            uint32_t* dst = &Ks[r * LDK + ch * 8];
            *(uint4*)dst = make_uint4(f2tf(a.x), f2tf(b.x),
                                      f2tf(a.y), f2tf(b.y));
            *(uint4*)(dst + 4) = make_uint4(f2tf(a.z), f2tf(b.z),
                                            f2tf(a.w), f2tf(b.w));
        }
        // ---- load V tile (row-pair layout): thread owns column tid ----
        #pragma unroll
        for (int blk = 0; blk < 8; blk++) {
            #pragma unroll
            for (int j = 0; j < 4; j++) {
                int r = blk * 8 + j;
                float v0 = V[(k0 + r)     * HD + tid];
                float v1 = V[(k0 + r + 4) * HD + tid];
                *(uint2*)&Vp[((r >> 3) * 4 + (r & 3)) * LDVP + 2 * tid] =
                    make_uint2(f2tf(v0), f2tf(v1));
            }
        }
        __syncthreads();

        // ---- S = (Q*scale) @ K^T : warp tile m16 x n64, Q from regs ----
        float sf[8][4];
        #pragma unroll
        for (int t = 0; t < 8; t++)
            #pragma unroll
            for (int j = 0; j < 4; j++) sf[t][j] = 0.0f;

        #pragma unroll
        for (int k = 0; k < 16; k++) {
            const int kc = k * 8;
            #pragma unroll
            for (int t = 0; t < 8; t++) {
                uint2 kbf = *(const uint2*)&Ks[(t * 8 + g) * LDK + kc + 2 * c4];
                mma_tf32(sf[t], qf0[k].x, qf1[k].x, qf0[k].y, qf1[k].y,
                         kbf.x, kbf.y);
            }
        }

        // ---- causal mask (diagonal tile only: k0 == q0) ----
        if (kt == nkv - 1) {
            const int r0 = q0 + mw + g;
            const int r1 = r0 + 8;
            #pragma unroll
            for (int t = 0; t < 8; t++) {
                const int cg0 = k0 + t * 8 + c4 * 2;
                if (cg0     > r0) sf[t][0] = -INFINITY;
                if (cg0 + 1 > r0) sf[t][1] = -INFINITY;
                if (cg0     > r1) sf[t][2] = -INFINITY;
                if (cg0 + 1 > r1) sf[t][3] = -INFINITY;
            }
        }

        // ---- online softmax (quad-local reduce) ----
        float mx0 = -INFINITY, mx1 = -INFINITY;
        #pragma unroll
        for (int t = 0; t < 8; t++) {
            mx0 = fmaxf(mx0, fmaxf(sf[t][0], sf[t][1]));
            mx1 = fmaxf(mx1, fmaxf(sf[t][2], sf[t][3]));
        }
        mx0 = fmaxf(mx0, __shfl_xor_sync(0xffffffffu, mx0, 1));
        mx0 = fmaxf(mx0, __shfl_xor_sync(0xffffffffu, mx0, 2));
        mx1 = fmaxf(mx1, __shfl_xor_sync(0xffffffffu, mx1, 1));
        mx1 = fmaxf(mx1, __shfl_xor_sync(0xffffffffu, mx1, 2));

        const float mn0 = fmaxf(m0, mx0);
        const float mn1 = fmaxf(m1, mx1);
        const float al0 = __expf(m0 - mn0);
        const float al1 = __expf(m1 - mn1);

        float s0 = 0.0f, s1 = 0.0f;
        #pragma unroll
        for (int t = 0; t < 8; t++) {
            sf[t][0] = __expf(sf[t][0] - mn0);
            sf[t][1] = __expf(sf[t][1] - mn0);
            sf[t][2] = __expf(sf[t][2] - mn1);
            sf[t][3] = __expf(sf[t][3] - mn1);
            s0 += sf[t][0] + sf[t][1];
            s1 += sf[t][2] + sf[t][3];
        }
        s0 += __shfl_xor_sync(0xffffffffu, s0, 1);
        s0 += __shfl_xor_sync(0xffffffffu, s0, 2);
        s1 += __shfl_xor_sync(0xffffffffu, s1, 1);
        s1 += __shfl_xor_sync(0xffffffffu, s1, 2);

        l0 = l0 * al0 + s0;  m0 = mn0;
        l1 = l1 * al1 + s1;  m1 = mn1;

        #pragma unroll
        for (int t = 0; t < 16; t++) {
            of[t][0] *= al0; of[t][1] *= al0;
            of[t][2] *= al1; of[t][3] *= al1;
        }

        // ---- store P in pair layout (warp-local rows) ----
        #pragma unroll
        for (int t = 0; t < 8; t++) {
            uint32_t* p0 = &Ps[(mw + g)     * LDP + t * 8 + poslo];
            uint32_t* p1 = &Ps[(mw + g + 8) * LDP + t * 8 + poslo];
            p0[0] = f2tf(sf[t][0]);  p0[2] = f2tf(sf[t][1]);
            p1[0] = f2tf(sf[t][2]);  p1[2] = f2tf(sf[t][3]);
        }
        __syncwarp();

        // ---- O += P @ V : warp tile m16 x n128, all LDS.64 ----
        #pragma unroll
        for (int k = 0; k < 8; k++) {
            const int kc = k * 8;
            uint2 pa = *(const uint2*)&Ps[(mw + g)     * LDP + kc + 2 * c4];
            uint2 pb = *(const uint2*)&Ps[(mw + g + 8) * LDP + kc + 2 * c4];
            #pragma unroll
            for (int t = 0; t < 16; t++) {
                uint2 vb = *(const uint2*)&Vp[(k * 4 + c4) * LDVP + 2 * (t * 8 + g)];
                mma_tf32(of[t], pa.x, pb.x, pa.y, pb.y, vb.x, vb.y);
            }
        }
        __syncthreads();   // all warps done with Ks/Vp before next tile load
    }

    // ---- epilogue ----
    const float inv0 = 1.0f / l0;
    const float inv1 = 1.0f / l1;
    const int r0 = q0 + mw + g;
    const int r1 = r0 + 8;
    #pragma unroll
    for (int t = 0; t < 16; t++) {
        const int col = t * 8 + c4 * 2;
        *(float2*)&O[r0 * HD + col] = make_float2(of[t][0] * inv0, of[t][1] * inv0);
        *(float2*)&O[r1 * HD + col] = make_float2(of[t][2] * inv1, of[t][3] * inv1);
    }
}

// ---------------------------------------------------------------------------
// Launch
// ---------------------------------------------------------------------------
extern "C" void kernel_launch(void* const* d_in, const int* in_sizes, int n_in,
                              void* d_out, int out_size)
{
    const float* x    = (const float*)d_in[0];  // [4,2048,128]
    const float* qkv  = (const float*)d_in[1];  // [128, 3072]
    const float* proj = (const float*)d_in[2];  // [1024, 128]
    float* out = (float*)d_out;                 // [4,2048,128]

    float *gq, *gk, *gv, *go;
    cudaGetSymbolAddress((void**)&gq, g_q);
    cudaGetSymbolAddress((void**)&gk, g_k);
    cudaGetSymbolAddress((void**)&gv, g_v);
    cudaGetSymbolAddress((void**)&go, g_o);

    const int M = HB * SEQ;          // 8192
    const int NQKV = NH * HD;        // 1024

    // Fused QKV: [8192,128] @ [128,3072], BN=64 tiles (2 CTAs/SM), split epilogue
    const int gemm_smem = (128 * 132 + 128 * 72) * (int)sizeof(uint32_t);  // 104,448
    cudaFuncSetAttribute(tf32_gemm_kernel<64, 1>,
                         cudaFuncAttributeMaxDynamicSharedMemorySize, gemm_smem);
    tf32_gemm_kernel<64, 1><<<dim3(3 * NQKV / 64, M / 128), 256, gemm_smem>>>(
        x, HD, qkv, 3 * NQKV, gq, gk, gv, NQKV, NQKV);

    // Flash attention: 32 heads x 32 q-tiles, 128 threads, 2 CTAs/SM
    const int flash_smem = SMEM_WORDS * (int)sizeof(uint32_t);  // 87,040 B
    cudaFuncSetAttribute(flash_tf32_kernel,
                         cudaFuncAttributeMaxDynamicSharedMemorySize, flash_smem);
    flash_tf32_kernel<<<dim3(HEADS, SEQ / BQ), 128, flash_smem>>>(gq, gk, gv, go);

    // Projection: [8192,1024] @ [1024,128], BN=64, 8 k-iterations
    cudaFuncSetAttribute(tf32_gemm_kernel<64, 8>,
                         cudaFuncAttributeMaxDynamicSharedMemorySize, gemm_smem);
    tf32_gemm_kernel<64, 8><<<dim3(HD / 64, M / 128), 256, gemm_smem>>>(
        go, NQKV, proj, HD, out, out, out, HD, 1 << 30);
}

// round 8
// speedup vs baseline: 1.0670x; 1.0670x over previous
#include <cuda_runtime.h>
#include <math.h>
#include <stdint.h>

// Problem constants (B=4, S=2048, H=128, NH=8)
#define HB 4
#define SEQ 2048
#define HD 128
#define NH 8
#define HEADS (HB * NH)            // 32
#define HEADELEMS (SEQ * HD)       // 262144
#define YELEMS (HB * SEQ * NH * HD) // 8388608

// Scratch (device globals: allocation-free per harness rules)
__device__ float g_q[YELEMS];
__device__ float g_k[YELEMS];
__device__ float g_v[YELEMS];
__device__ float g_o[YELEMS];

__device__ __forceinline__ uint32_t f2tf(float f) {
    uint32_t u;
    asm("cvt.rna.tf32.f32 %0, %1;" : "=r"(u) : "f"(f));
    return u;
}

__device__ __forceinline__ void mma_tf32(float c[4],
    uint32_t a0, uint32_t a1, uint32_t a2, uint32_t a3,
    uint32_t b0, uint32_t b1)
{
    asm volatile(
        "mma.sync.aligned.m16n8k8.row.col.f32.tf32.tf32.f32 "
        "{%0,%1,%2,%3}, {%4,%5,%6,%7}, {%8,%9}, {%0,%1,%2,%3};\n"
        : "+f"(c[0]), "+f"(c[1]), "+f"(c[2]), "+f"(c[3])
        : "r"(a0), "r"(a1), "r"(a2), "r"(a3), "r"(b0), "r"(b1));
}

// ---------------------------------------------------------------------------
// TF32 GEMM v2: pair-interleaved smem, all fragment loads LDS.64.
// A: within-row pair layout, ld=136  (word(c) = (c&~7) + 2*(c&3) + ((c>>2)&1))
// B: row-pair layout (like flash V): Bp[(r>>3)*4+(r&3)][2*n + ((r>>2)&1)], ld=136
// BM=128 (8 warps x m16), BK=128/iter, BN=64. smem=104,448B -> 2 CTAs/SM.
// MMA order identical to v1 -> bit-identical results.
// ---------------------------------------------------------------------------
#define GLD 136

template<int NKITER>
__global__ __launch_bounds__(256, 2)
void tf32_gemm_kernel(const float* __restrict__ A, int lda,
                      const float* __restrict__ B, int ldb,
                      float* __restrict__ C0, float* __restrict__ C1,
                      float* __restrict__ C2, int ldc, int segW)
{
    constexpr int BM = 128;
    constexpr int BK = 128;
    constexpr int BN = 64;
    constexpr int NT = BN / 8;

    extern __shared__ uint32_t smg[];
    uint32_t* As = smg;                 // BM x GLD (pair-interleaved rows)
    uint32_t* Bp = smg + BM * GLD;      // 64 x GLD (row-pair layout)

    const int tid  = threadIdx.x;
    const int lane = tid & 31;
    const int g    = lane >> 2;
    const int c4   = lane & 3;
    const int mw   = (tid >> 5) * 16;

    const int row0 = blockIdx.y * BM;
    const int colg = blockIdx.x * BN;
    const int seg  = colg / segW;
    float* C = (seg == 0) ? C0 : ((seg == 1) ? C1 : C2);
    const int coll = colg - seg * segW;

    // B loader mapping: thread owns column n, rows [rb, rb+32)
    const int bn = tid & 63;
    const int rb = (tid >> 6) * 32;

    float acc[NT][4];
    #pragma unroll
    for (int t = 0; t < NT; t++)
        #pragma unroll
        for (int j = 0; j < 4; j++) acc[t][j] = 0.0f;

    for (int kt = 0; kt < NKITER; kt++) {
        const int k0 = kt * BK;

        // ---- load A tile (BM x BK) into pair layout ----
        #pragma unroll
        for (int t8 = 0; t8 < 8; t8++) {
            int cid = t8 * 256 + tid;       // 128 rows x 16 chunks
            int r = cid >> 4, ch = cid & 15;
            const float* src = &A[(long)(row0 + r) * lda + k0 + ch * 8];
            float4 a = *(const float4*)src;
            float4 b = *(const float4*)(src + 4);
            uint32_t* dst = &As[r * GLD + ch * 8];
            *(uint4*)dst = make_uint4(f2tf(a.x), f2tf(b.x),
                                      f2tf(a.y), f2tf(b.y));
            *(uint4*)(dst + 4) = make_uint4(f2tf(a.z), f2tf(b.z),
                                            f2tf(a.w), f2tf(b.w));
        }
        // ---- load B tile (BK x BN) into row-pair layout ----
        #pragma unroll
        for (int blk = 0; blk < 4; blk++) {
            #pragma unroll
            for (int j = 0; j < 4; j++) {
                int r = rb + blk * 8 + j;
                float v0 = B[(long)(k0 + r)     * ldb + colg + bn];
                float v1 = B[(long)(k0 + r + 4) * ldb + colg + bn];
                *(uint2*)&Bp[((r >> 3) * 4 + (r & 3)) * GLD + 2 * bn] =
                    make_uint2(f2tf(v0), f2tf(v1));
            }
        }
        __syncthreads();

        #pragma unroll
        for (int kcix = 0; kcix < BK / 8; kcix++) {
            const int kc = kcix * 8;
            uint2 aa = *(const uint2*)&As[(mw + g)     * GLD + kc + 2 * c4]; // a0,a2
            uint2 ab = *(const uint2*)&As[(mw + g + 8) * GLD + kc + 2 * c4]; // a1,a3
            #pragma unroll
            for (int t = 0; t < NT; t++) {
                uint2 bb = *(const uint2*)&Bp[(kcix * 4 + c4) * GLD + 2 * (t * 8 + g)];
                mma_tf32(acc[t], aa.x, ab.x, aa.y, ab.y, bb.x, bb.y);
            }
        }
        __syncthreads();
    }

    const int r0 = row0 + mw + g;
    const int r1 = r0 + 8;
    #pragma unroll
    for (int t = 0; t < NT; t++) {
        const int col = coll + t * 8 + c4 * 2;
        *(float2*)&C[(long)r0 * ldc + col] = make_float2(acc[t][0], acc[t][1]);
        *(float2*)&C[(long)r1 * ldc + col] = make_float2(acc[t][2], acc[t][3]);
    }
}

// ---------------------------------------------------------------------------
// TF32 flash attention (round-6 version, verbatim): BQ=128, 256 threads,
// pair-interleaved smem (all fragment loads LDS.64) + register prefetch
// double-buffering of K/V tiles.
// ---------------------------------------------------------------------------
#define BQ 128
#define BKV 64
#define LDQ 136
#define LDK 136
#define LDVP 264
#define LDP 72

#define QS_OFF 0
#define KS_OFF (BQ * LDQ)                    // 17408
#define VP_OFF (KS_OFF + BKV * LDK)          // 26112
#define PS_OFF (VP_OFF + 32 * LDVP)          // 34560
#define SMEM_WORDS (PS_OFF + BQ * LDP)       // 43776 words = 175104 B

__global__ __launch_bounds__(256, 1)
void flash_tf32_kernel(const float* __restrict__ gq, const float* __restrict__ gk,
                       const float* __restrict__ gv, float* __restrict__ go)
{
    extern __shared__ uint32_t sm[];
    uint32_t* Qs = sm + QS_OFF;
    uint32_t* Ks = sm + KS_OFF;
    uint32_t* Vp = sm + VP_OFF;
    uint32_t* Ps = sm + PS_OFF;

    const int tid  = threadIdx.x;
    const int lane = tid & 31;
    const int g    = lane >> 2;
    const int c4   = lane & 3;
    const int mw   = (tid >> 5) * 16;

    const int hb = blockIdx.x;
    const int qt = (int)gridDim.y - 1 - (int)blockIdx.y;
    const int q0 = qt * BQ;

    const float* Q = gq + (long)hb * HEADELEMS;
    const float* K = gk + (long)hb * HEADELEMS;
    const float* V = gv + (long)hb * HEADELEMS;
    float*       O = go + (long)hb * HEADELEMS;

    const float scale = 0.08838834764831845f;  // 1/sqrt(128)

    // ---- stage Q (pre-scaled) into pair layout: 8 chunks/thread ----
    #pragma unroll
    for (int t8 = 0; t8 < 8; t8++) {
        int cid = t8 * 256 + tid;
        int r = cid >> 4, ch = cid & 15;
        const float* src = &Q[(q0 + r) * HD + ch * 8];
        float4 a = *(const float4*)src;
        float4 b = *(const float4*)(src + 4);
        uint32_t* dst = &Qs[r * LDQ + ch * 8];
        *(uint4*)dst = make_uint4(f2tf(a.x * scale), f2tf(b.x * scale),
                                  f2tf(a.y * scale), f2tf(b.y * scale));
        *(uint4*)(dst + 4) = make_uint4(f2tf(a.z * scale), f2tf(b.z * scale),
                                        f2tf(a.w * scale), f2tf(b.w * scale));
    }

    // V loader mapping: thread owns column vc, rows [vk0, vk0+32)
    const int vc  = tid & 127;
    const int vk0 = (tid >> 7) * 32;

    const int nkv = (q0 + BQ) / BKV;

    // ---- prime tile 0 ----
    float4 ka[4], kb[4];
    float  vr[32];
    {
        #pragma unroll
        for (int t4 = 0; t4 < 4; t4++) {
            int cid = t4 * 256 + tid;
            int r = cid >> 4, ch = cid & 15;
            const float* src = &K[r * HD + ch * 8];
            ka[t4] = *(const float4*)src;
            kb[t4] = *(const float4*)(src + 4);
        }
        #pragma unroll
        for (int i = 0; i < 32; i++)
            vr[i] = V[(vk0 + i) * HD + vc];

        #pragma unroll
        for (int t4 = 0; t4 < 4; t4++) {
            int cid = t4 * 256 + tid;
            int r = cid >> 4, ch = cid & 15;
            uint32_t* dst = &Ks[r * LDK + ch * 8];
            *(uint4*)dst = make_uint4(f2tf(ka[t4].x), f2tf(kb[t4].x),
                                      f2tf(ka[t4].y), f2tf(kb[t4].y));
            *(uint4*)(dst + 4) = make_uint4(f2tf(ka[t4].z), f2tf(kb[t4].z),
                                            f2tf(ka[t4].w), f2tf(kb[t4].w));
        }
        #pragma unroll
        for (int i = 0; i < 32; i++) {
            int r = vk0 + i;
            Vp[((r >> 3) * 4 + (r & 3)) * LDVP + 2 * vc + ((r >> 2) & 1)] = f2tf(vr[i]);
        }
    }
    __syncthreads();

    float of[16][4];
    #pragma unroll
    for (int t = 0; t < 16; t++)
        #pragma unroll
        for (int j = 0; j < 4; j++) of[t][j] = 0.0f;
    float m0 = -INFINITY, m1 = -INFINITY, l0 = 0.0f, l1 = 0.0f;

    const int poslo = ((c4 & 1) << 2) | (c4 >> 1);   // P pair position for col 2*c4

    for (int kt = 0; kt < nkv; kt++) {
        const bool more = (kt + 1 < nkv);

        // ---- prefetch next K tile into registers ----
        if (more) {
            const int kn = (kt + 1) * BKV;
            #pragma unroll
            for (int t4 = 0; t4 < 4; t4++) {
                int cid = t4 * 256 + tid;
                int r = cid >> 4, ch = cid & 15;
                const float* src = &K[(kn + r) * HD + ch * 8];
                ka[t4] = *(const float4*)src;
                kb[t4] = *(const float4*)(src + 4);
            }
        }

        // ---- S = (Q*scale) @ K^T : warp tile m16 x n64, all LDS.64 ----
        float sf[8][4];
        #pragma unroll
        for (int t = 0; t < 8; t++)
            #pragma unroll
            for (int j = 0; j < 4; j++) sf[t][j] = 0.0f;

        #pragma unroll
        for (int k = 0; k < 16; k++) {
            const int kc = k * 8;
            uint2 qa = *(const uint2*)&Qs[(mw + g)     * LDQ + kc + 2 * c4]; // a0,a2
            uint2 qb = *(const uint2*)&Qs[(mw + g + 8) * LDQ + kc + 2 * c4]; // a1,a3
            #pragma unroll
            for (int t = 0; t < 8; t++) {
                uint2 kbf = *(const uint2*)&Ks[(t * 8 + g) * LDK + kc + 2 * c4];
                mma_tf32(sf[t], qa.x, qb.x, qa.y, qb.y, kbf.x, kbf.y);
            }
        }

        // ---- causal mask (tiles touching the diagonal) ----
        if (kt >= nkv - 2) {
            const int k0 = kt * BKV;
            const int r0 = q0 + mw + g;
            const int r1 = r0 + 8;
            #pragma unroll
            for (int t = 0; t < 8; t++) {
                const int cg0 = k0 + t * 8 + c4 * 2;
                if (cg0     > r0) sf[t][0] = -INFINITY;
                if (cg0 + 1 > r0) sf[t][1] = -INFINITY;
                if (cg0     > r1) sf[t][2] = -INFINITY;
                if (cg0 + 1 > r1) sf[t][3] = -INFINITY;
            }
        }

        __syncthreads();   // all warps done reading Ks

        // ---- store prefetched K into Ks (pair layout) ----
        if (more) {
            #pragma unroll
            for (int t4 = 0; t4 < 4; t4++) {
                int cid = t4 * 256 + tid;
                int r = cid >> 4, ch = cid & 15;
                uint32_t* dst = &Ks[r * LDK + ch * 8];
                *(uint4*)dst = make_uint4(f2tf(ka[t4].x), f2tf(kb[t4].x),
                                          f2tf(ka[t4].y), f2tf(kb[t4].y));
                *(uint4*)(dst + 4) = make_uint4(f2tf(ka[t4].z), f2tf(kb[t4].z),
                                                f2tf(ka[t4].w), f2tf(kb[t4].w));
            }
        }

        // ---- online softmax (quad-local reduce) ----
        float mx0 = -INFINITY, mx1 = -INFINITY;
        #pragma unroll
        for (int t = 0; t < 8; t++) {
            mx0 = fmaxf(mx0, fmaxf(sf[t][0], sf[t][1]));
            mx1 = fmaxf(mx1, fmaxf(sf[t][2], sf[t][3]));
        }
        mx0 = fmaxf(mx0, __shfl_xor_sync(0xffffffffu, mx0, 1));
        mx0 = fmaxf(mx0, __shfl_xor_sync(0xffffffffu, mx0, 2));
        mx1 = fmaxf(mx1, __shfl_xor_sync(0xffffffffu, mx1, 1));
        mx1 = fmaxf(mx1, __shfl_xor_sync(0xffffffffu, mx1, 2));

        const float mn0 = fmaxf(m0, mx0);
        const float mn1 = fmaxf(m1, mx1);
        const float al0 = __expf(m0 - mn0);
        const float al1 = __expf(m1 - mn1);

        float s0 = 0.0f, s1 = 0.0f;
        #pragma unroll
        for (int t = 0; t < 8; t++) {
            sf[t][0] = __expf(sf[t][0] - mn0);
            sf[t][1] = __expf(sf[t][1] - mn0);
            sf[t][2] = __expf(sf[t][2] - mn1);
            sf[t][3] = __expf(sf[t][3] - mn1);
            s0 += sf[t][0] + sf[t][1];
            s1 += sf[t][2] + sf[t][3];
        }
        s0 += __shfl_xor_sync(0xffffffffu, s0, 1);
        s0 += __shfl_xor_sync(0xffffffffu, s0, 2);
        s1 += __shfl_xor_sync(0xffffffffu, s1, 1);
        s1 += __shfl_xor_sync(0xffffffffu, s1, 2);

        l0 = l0 * al0 + s0;  m0 = mn0;
        l1 = l1 * al1 + s1;  m1 = mn1;

        #pragma unroll
        for (int t = 0; t < 16; t++) {
            of[t][0] *= al0; of[t][1] *= al0;
            of[t][2] *= al1; of[t][3] *= al1;
        }

        // ---- store P in pair layout (warp-local rows) ----
        #pragma unroll
        for (int t = 0; t < 8; t++) {
            uint32_t* p0 = &Ps[(mw + g)     * LDP + t * 8 + poslo];
            uint32_t* p1 = &Ps[(mw + g + 8) * LDP + t * 8 + poslo];
            p0[0] = f2tf(sf[t][0]);  p0[2] = f2tf(sf[t][1]);
            p1[0] = f2tf(sf[t][2]);  p1[2] = f2tf(sf[t][3]);
        }
        __syncwarp();

        // ---- prefetch next V tile into registers ----
        if (more) {
            const int kn = (kt + 1) * BKV;
            #pragma unroll
            for (int i = 0; i < 32; i++)
                vr[i] = V[(kn + vk0 + i) * HD + vc];
        }

        // ---- O += P @ V : warp tile m16 x n128, all LDS.64 ----
        #pragma unroll
        for (int k = 0; k < 8; k++) {
            const int kc = k * 8;
            uint2 pa = *(const uint2*)&Ps[(mw + g)     * LDP + kc + 2 * c4];
            uint2 pb = *(const uint2*)&Ps[(mw + g + 8) * LDP + kc + 2 * c4];
            #pragma unroll
            for (int t = 0; t < 16; t++) {
                uint2 vb = *(const uint2*)&Vp[(k * 4 + c4) * LDVP + 2 * (t * 8 + g)];
                mma_tf32(of[t], pa.x, pb.x, pa.y, pb.y, vb.x, vb.y);
            }
        }

        __syncthreads();   // all warps done reading Vp (and orders Ks stores)

        // ---- store prefetched V into Vp (pair layout) ----
        if (more) {
            #pragma unroll
            for (int i = 0; i < 32; i++) {
                int r = vk0 + i;
                Vp[((r >> 3) * 4 + (r & 3)) * LDVP + 2 * vc + ((r >> 2) & 1)] = f2tf(vr[i]);
            }
        }
    }

    // ---- epilogue ----
    const float inv0 = 1.0f / l0;
    const float inv1 = 1.0f / l1;
    const int r0 = q0 + mw + g;
    const int r1 = r0 + 8;
    #pragma unroll
    for (int t = 0; t < 16; t++) {
        const int col = t * 8 + c4 * 2;
        *(float2*)&O[r0 * HD + col] = make_float2(of[t][0] * inv0, of[t][1] * inv0);
        *(float2*)&O[r1 * HD + col] = make_float2(of[t][2] * inv1, of[t][3] * inv1);
    }
}

// ---------------------------------------------------------------------------
// Launch
// ---------------------------------------------------------------------------
extern "C" void kernel_launch(void* const* d_in, const int* in_sizes, int n_in,
                              void* d_out, int out_size)
{
    const float* x    = (const float*)d_in[0];  // [4,2048,128]
    const float* qkv  = (const float*)d_in[1];  // [128, 3072]
    const float* proj = (const float*)d_in[2];  // [1024, 128]
    float* out = (float*)d_out;                 // [4,2048,128]

    float *gq, *gk, *gv, *go;
    cudaGetSymbolAddress((void**)&gq, g_q);
    cudaGetSymbolAddress((void**)&gk, g_k);
    cudaGetSymbolAddress((void**)&gv, g_v);
    cudaGetSymbolAddress((void**)&go, g_o);

    const int M = HB * SEQ;          // 8192
    const int NQKV = NH * HD;        // 1024

    // Fused QKV: [8192,128] @ [128,3072], BN=64 tiles, split epilogue
    const int gemm_smem = (128 * GLD + 64 * GLD) * (int)sizeof(uint32_t);  // 104,448
    cudaFuncSetAttribute(tf32_gemm_kernel<1>,
                         cudaFuncAttributeMaxDynamicSharedMemorySize, gemm_smem);
    tf32_gemm_kernel<1><<<dim3(3 * NQKV / 64, M / 128), 256, gemm_smem>>>(
        x, HD, qkv, 3 * NQKV, gq, gk, gv, NQKV, NQKV);

    // Flash attention: 32 heads x 16 q-tiles, 256 threads
    const int flash_smem = SMEM_WORDS * (int)sizeof(uint32_t);  // 175,104 B
    cudaFuncSetAttribute(flash_tf32_kernel,
                         cudaFuncAttributeMaxDynamicSharedMemorySize, flash_smem);
    flash_tf32_kernel<<<dim3(HEADS, SEQ / BQ), 256, flash_smem>>>(gq, gk, gv, go);

    // Projection: [8192,1024] @ [1024,128], 8 k-iterations
    cudaFuncSetAttribute(tf32_gemm_kernel<8>,
                         cudaFuncAttributeMaxDynamicSharedMemorySize, gemm_smem);
    tf32_gemm_kernel<8><<<dim3(HD / 64, M / 128), 256, gemm_smem>>>(
        go, NQKV, proj, HD, out, out, out, HD, 1 << 30);
}

// round 10
// speedup vs baseline: 1.2721x; 1.1922x over previous
#include <cuda_runtime.h>
#include <cuda_fp16.h>
#include <math.h>
#include <stdint.h>

// Problem constants (B=4, S=2048, H=128, NH=8)
#define HB 4
#define SEQ 2048
#define HD 128
#define NH 8
#define HEADS (HB * NH)            // 32
#define HEADELEMS (SEQ * HD)       // 262144
#define YELEMS (HB * SEQ * NH * HD) // 8388608

// Scratch (device globals: allocation-free per harness rules)
__device__ float g_q[YELEMS];
__device__ float g_k[YELEMS];
__device__ float g_v[YELEMS];
__device__ float g_o[YELEMS];

__device__ __forceinline__ uint32_t f2h2(float lo, float hi) {
    __half2 h = __floats2half2_rn(lo, hi);
    return *reinterpret_cast<uint32_t*>(&h);
}

__device__ __forceinline__ void mma_f16(float c[4],
    uint32_t a0, uint32_t a1, uint32_t a2, uint32_t a3,
    uint32_t b0, uint32_t b1)
{
    asm volatile(
        "mma.sync.aligned.m16n8k16.row.col.f32.f16.f16.f32 "
        "{%0,%1,%2,%3}, {%4,%5,%6,%7}, {%8,%9}, {%0,%1,%2,%3};\n"
        : "+f"(c[0]), "+f"(c[1]), "+f"(c[2]), "+f"(c[3])
        : "r"(a0), "r"(a1), "r"(a2), "r"(a3), "r"(b0), "r"(b1));
}

// Chunk interleave: 16 consecutive floats (one k16 chunk) -> 8 half2 words
// stored as [w0,w4,w1,w5,w2,w6,w3,w7]; a uint2 read at word 2*c4 then yields
// {w[c4], w[c4+4]} = the fp16 MMA fragment pair.
#define STORE_CHUNK(dst, A, B_, C_, D_)                                   \
    do {                                                                   \
        ((uint4*)(dst))[0] = make_uint4(f2h2((A).x,(A).y), f2h2((C_).x,(C_).y), \
                                        f2h2((A).z,(A).w), f2h2((C_).z,(C_).w)); \
        ((uint4*)(dst))[1] = make_uint4(f2h2((B_).x,(B_).y), f2h2((D_).x,(D_).y), \
                                        f2h2((B_).z,(B_).w), f2h2((D_).z,(D_).w)); \
    } while (0)

// ---------------------------------------------------------------------------
// FP16 tensor-core GEMM: C = A[M,K] @ B[K,N] (fp32 in/out, fp32 accum).
// BM=128 (8 warps x m16), BK=128/iter (8 k16-chunks), BN=64 (NT=8).
// A: chunk-interleaved rows, ld=68 words. B: row-pair layout, 32 x 136 words.
// smem = 52,224 B -> 2 CTAs/SM.
// ---------------------------------------------------------------------------
#define GA_LD 68
#define GB_LD 136

template<int NKITER>
__global__ __launch_bounds__(256, 2)
void f16_gemm_kernel(const float* __restrict__ A, int lda,
                     const float* __restrict__ B, int ldb,
                     float* __restrict__ C0, float* __restrict__ C1,
                     float* __restrict__ C2, int ldc, int segW)
{
    constexpr int BM = 128;
    constexpr int NT = 8;

    extern __shared__ uint32_t smg[];
    uint32_t* As = smg;                 // 128 x 68
    uint32_t* Bq = smg + BM * GA_LD;    // 32 x 136

    const int tid  = threadIdx.x;
    const int lane = tid & 31;
    const int g    = lane >> 2;
    const int c4   = lane & 3;
    const int mw   = (tid >> 5) * 16;

    const int row0 = blockIdx.y * BM;
    const int colg = blockIdx.x * 64;
    const int seg  = colg / segW;
    float* C = (seg == 0) ? C0 : ((seg == 1) ? C1 : C2);
    const int coll = colg - seg * segW;

    const int bn = tid & 63;            // B loader: column
    const int cg = tid >> 6;            // B loader: chunk group (2 chunks)

    float acc[NT][4];
    #pragma unroll
    for (int t = 0; t < NT; t++)
        #pragma unroll
        for (int j = 0; j < 4; j++) acc[t][j] = 0.0f;

    for (int kt = 0; kt < NKITER; kt++) {
        const int k0 = kt * 128;

        // ---- A tile: 4 chunks/thread ----
        #pragma unroll
        for (int t4 = 0; t4 < 4; t4++) {
            int cid = t4 * 256 + tid;
            int r = cid >> 3, ch = cid & 7;
            const float* src = &A[(long)(row0 + r) * lda + k0 + ch * 16];
            float4 a = *(const float4*)src;
            float4 b = *(const float4*)(src + 4);
            float4 c = *(const float4*)(src + 8);
            float4 d = *(const float4*)(src + 12);
            STORE_CHUNK(&As[r * GA_LD + ch * 8], a, b, c, d);
        }
        // ---- B tile: row-pair layout, 2 chunks/thread, 1 column ----
        #pragma unroll
        for (int ci = 0; ci < 2; ci++) {
            int ch = 2 * cg + ci;
            #pragma unroll
            for (int i = 0; i < 4; i++) {
                int rg = k0 + ch * 16 + 2 * i;
                float lo0 = B[(long)rg * ldb + colg + bn];
                float lo1 = B[(long)(rg + 1) * ldb + colg + bn];
                float hi0 = B[(long)(rg + 8) * ldb + colg + bn];
                float hi1 = B[(long)(rg + 9) * ldb + colg + bn];
                *(uint2*)&Bq[(ch * 4 + i) * GB_LD + 2 * bn] =
                    make_uint2(f2h2(lo0, lo1), f2h2(hi0, hi1));
            }
        }
        __syncthreads();

        #pragma unroll
        for (int kc = 0; kc < 8; kc++) {
            uint2 aa = *(const uint2*)&As[(mw + g)     * GA_LD + kc * 8 + 2 * c4];
            uint2 ab = *(const uint2*)&As[(mw + g + 8) * GA_LD + kc * 8 + 2 * c4];
            #pragma unroll
            for (int t = 0; t < NT; t++) {
                uint2 bb = *(const uint2*)&Bq[(kc * 4 + c4) * GB_LD + 2 * (t * 8 + g)];
                mma_f16(acc[t], aa.x, ab.x, aa.y, ab.y, bb.x, bb.y);
            }
        }
        __syncthreads();
    }

    const int r0 = row0 + mw + g;
    const int r1 = r0 + 8;
    #pragma unroll
    for (int t = 0; t < NT; t++) {
        const int col = coll + t * 8 + c4 * 2;
        *(float2*)&C[(long)r0 * ldc + col] = make_float2(acc[t][0], acc[t][1]);
        *(float2*)&C[(long)r1 * ldc + col] = make_float2(acc[t][2], acc[t][3]);
    }
}

// ---------------------------------------------------------------------------
// FP16 flash attention: BQ=128, 256 threads, R6 structure (reg prefetch of
// K/V) with fp16 m16n8k16 fragments. All smem in uint32 = half2 words.
// Q/K: chunk-interleaved rows (ld=68). V: row-pair (16 x 264). P: 128 x 36.
// smem = 87,552 B.
// ---------------------------------------------------------------------------
#define BQ 128
#define BKV 64
#define LDQ 68
#define LDK 68
#define LDVQ 264
#define LDP 36

#define QS_OFF 0
#define KS_OFF (BQ * LDQ)                    // 8704
#define VQ_OFF (KS_OFF + BKV * LDK)          // 13056
#define PS_OFF (VQ_OFF + 16 * LDVQ)          // 17280
#define SMEM_WORDS (PS_OFF + BQ * LDP)       // 21888 words = 87552 B

__global__ __launch_bounds__(256, 1)
void flash_f16_kernel(const float* __restrict__ gq, const float* __restrict__ gk,
                      const float* __restrict__ gv, float* __restrict__ go)
{
    extern __shared__ uint32_t sm[];
    uint32_t* Qs = sm + QS_OFF;
    uint32_t* Ks = sm + KS_OFF;
    uint32_t* Vq = sm + VQ_OFF;
    uint32_t* Ps = sm + PS_OFF;

    const int tid  = threadIdx.x;
    const int lane = tid & 31;
    const int g    = lane >> 2;
    const int c4   = lane & 3;
    const int mw   = (tid >> 5) * 16;

    const int hb = blockIdx.x;
    const int qt = (int)gridDim.y - 1 - (int)blockIdx.y;
    const int q0 = qt * BQ;

    const float* Q = gq + (long)hb * HEADELEMS;
    const float* K = gk + (long)hb * HEADELEMS;
    const float* V = gv + (long)hb * HEADELEMS;
    float*       O = go + (long)hb * HEADELEMS;

    const float scale = 0.08838834764831845f;  // 1/sqrt(128)

    // ---- stage Q (pre-scaled) : 4 chunks/thread ----
    #pragma unroll
    for (int t4 = 0; t4 < 4; t4++) {
        int cid = t4 * 256 + tid;
        int r = cid >> 3, ch = cid & 7;
        const float* src = &Q[(q0 + r) * HD + ch * 16];
        float4 a = *(const float4*)src;
        float4 b = *(const float4*)(src + 4);
        float4 c = *(const float4*)(src + 8);
        float4 d = *(const float4*)(src + 12);
        a.x *= scale; a.y *= scale; a.z *= scale; a.w *= scale;
        b.x *= scale; b.y *= scale; b.z *= scale; b.w *= scale;
        c.x *= scale; c.y *= scale; c.z *= scale; c.w *= scale;
        d.x *= scale; d.y *= scale; d.z *= scale; d.w *= scale;
        STORE_CHUNK(&Qs[r * LDQ + ch * 8], a, b, c, d);
    }

    // V loader: thread owns column vc, chunk pair vh
    const int vc = tid & 127;
    const int vh = tid >> 7;             // chunks {2vh, 2vh+1}

    const int nkv = (q0 + BQ) / BKV;

    // ---- prime tile 0 ----
    float4 kf[8];                        // 2 chunks (K)
    float  vr[32];                       // 32 rows of one V column
    {
        #pragma unroll
        for (int t2 = 0; t2 < 2; t2++) {
            int cid = t2 * 256 + tid;
            int r = cid >> 3, ch = cid & 7;
            const float* src = &K[r * HD + ch * 16];
            kf[t2*4+0] = *(const float4*)src;
            kf[t2*4+1] = *(const float4*)(src + 4);
            kf[t2*4+2] = *(const float4*)(src + 8);
            kf[t2*4+3] = *(const float4*)(src + 12);
        }
        #pragma unroll
        for (int i = 0; i < 32; i++)
            vr[i] = V[(vh * 32 + i) * HD + vc];

        #pragma unroll
        for (int t2 = 0; t2 < 2; t2++) {
            int cid = t2 * 256 + tid;
            int r = cid >> 3, ch = cid & 7;
            STORE_CHUNK(&Ks[r * LDK + ch * 8],
                        kf[t2*4+0], kf[t2*4+1], kf[t2*4+2], kf[t2*4+3]);
        }
        #pragma unroll
        for (int ci = 0; ci < 2; ci++) {
            int ch = 2 * vh + ci;
            #pragma unroll
            for (int i = 0; i < 4; i++) {
                *(uint2*)&Vq[(ch * 4 + i) * LDVQ + 2 * vc] =
                    make_uint2(f2h2(vr[ci*16 + 2*i],     vr[ci*16 + 2*i + 1]),
                               f2h2(vr[ci*16 + 2*i + 8], vr[ci*16 + 2*i + 9]));
            }
        }
    }
    __syncthreads();

    float of[16][4];
    #pragma unroll
    for (int t = 0; t < 16; t++)
        #pragma unroll
        for (int j = 0; j < 4; j++) of[t][j] = 0.0f;
    float m0 = -INFINITY, m1 = -INFINITY, l0 = 0.0f, l1 = 0.0f;

    for (int kt = 0; kt < nkv; kt++) {
        const bool more = (kt + 1 < nkv);

        // ---- prefetch next K tile into registers ----
        if (more) {
            const int kn = (kt + 1) * BKV;
            #pragma unroll
            for (int t2 = 0; t2 < 2; t2++) {
                int cid = t2 * 256 + tid;
                int r = cid >> 3, ch = cid & 7;
                const float* src = &K[(kn + r) * HD + ch * 16];
                kf[t2*4+0] = *(const float4*)src;
                kf[t2*4+1] = *(const float4*)(src + 4);
                kf[t2*4+2] = *(const float4*)(src + 8);
                kf[t2*4+3] = *(const float4*)(src + 12);
            }
        }

        // ---- S = (Q*scale) @ K^T : warp m16 x n64, 8 k16-chunks ----
        float sf[8][4];
        #pragma unroll
        for (int t = 0; t < 8; t++)
            #pragma unroll
            for (int j = 0; j < 4; j++) sf[t][j] = 0.0f;

        #pragma unroll
        for (int k = 0; k < 8; k++) {
            uint2 qa = *(const uint2*)&Qs[(mw + g)     * LDQ + k * 8 + 2 * c4];
            uint2 qb = *(const uint2*)&Qs[(mw + g + 8) * LDQ + k * 8 + 2 * c4];
            #pragma unroll
            for (int t = 0; t < 8; t++) {
                uint2 kb = *(const uint2*)&Ks[(t * 8 + g) * LDK + k * 8 + 2 * c4];
                mma_f16(sf[t], qa.x, qb.x, qa.y, qb.y, kb.x, kb.y);
            }
        }

        // ---- causal mask (tiles touching the diagonal) ----
        if (kt >= nkv - 2) {
            const int k0 = kt * BKV;
            const int r0 = q0 + mw + g;
            const int r1 = r0 + 8;
            #pragma unroll
            for (int t = 0; t < 8; t++) {
                const int cg0 = k0 + t * 8 + c4 * 2;
                if (cg0     > r0) sf[t][0] = -INFINITY;
                if (cg0 + 1 > r0) sf[t][1] = -INFINITY;
                if (cg0     > r1) sf[t][2] = -INFINITY;
                if (cg0 + 1 > r1) sf[t][3] = -INFINITY;
            }
        }

        __syncthreads();   // all warps done reading Ks

        // ---- store prefetched K ----
        if (more) {
            #pragma unroll
            for (int t2 = 0; t2 < 2; t2++) {
                int cid = t2 * 256 + tid;
                int r = cid >> 3, ch = cid & 7;
                STORE_CHUNK(&Ks[r * LDK + ch * 8],
                            kf[t2*4+0], kf[t2*4+1], kf[t2*4+2], kf[t2*4+3]);
            }
        }

        // ---- online softmax (quad-local reduce) ----
        float mx0 = -INFINITY, mx1 = -INFINITY;
        #pragma unroll
        for (int t = 0; t < 8; t++) {
            mx0 = fmaxf(mx0, fmaxf(sf[t][0], sf[t][1]));
            mx1 = fmaxf(mx1, fmaxf(sf[t][2], sf[t][3]));
        }
        mx0 = fmaxf(mx0, __shfl_xor_sync(0xffffffffu, mx0, 1));
        mx0 = fmaxf(mx0, __shfl_xor_sync(0xffffffffu, mx0, 2));
        mx1 = fmaxf(mx1, __shfl_xor_sync(0xffffffffu, mx1, 1));
        mx1 = fmaxf(mx1, __shfl_xor_sync(0xffffffffu, mx1, 2));

        const float mn0 = fmaxf(m0, mx0);
        const float mn1 = fmaxf(m1, mx1);
        const float al0 = __expf(m0 - mn0);
        const float al1 = __expf(m1 - mn1);

        float s0 = 0.0f, s1 = 0.0f;
        #pragma unroll
        for (int t = 0; t < 8; t++) {
            sf[t][0] = __expf(sf[t][0] - mn0);
            sf[t][1] = __expf(sf[t][1] - mn0);
            sf[t][2] = __expf(sf[t][2] - mn1);
            sf[t][3] = __expf(sf[t][3] - mn1);
            s0 += sf[t][0] + sf[t][1];
            s1 += sf[t][2] + sf[t][3];
        }
        s0 += __shfl_xor_sync(0xffffffffu, s0, 1);
        s0 += __shfl_xor_sync(0xffffffffu, s0, 2);
        s1 += __shfl_xor_sync(0xffffffffu, s1, 1);
        s1 += __shfl_xor_sync(0xffffffffu, s1, 2);

        l0 = l0 * al0 + s0;  m0 = mn0;
        l1 = l1 * al1 + s1;  m1 = mn1;

        #pragma unroll
        for (int t = 0; t < 16; t++) {
            of[t][0] *= al0; of[t][1] *= al0;
            of[t][2] *= al1; of[t][3] *= al1;
        }

        // ---- store P (fp16, interleaved chunk position) ----
        // cols t*8+2c4,+1 -> chunk t>>1, word pos (t&1) + 2*c4
        #pragma unroll
        for (int t = 0; t < 8; t++) {
            const int wp = (t >> 1) * 8 + 2 * c4 + (t & 1);
            Ps[(mw + g)     * LDP + wp] = f2h2(sf[t][0], sf[t][1]);
            Ps[(mw + g + 8) * LDP + wp] = f2h2(sf[t][2], sf[t][3]);
        }
        __syncwarp();

        // ---- prefetch next V tile into registers ----
        if (more) {
            const int kn = (kt + 1) * BKV;
            #pragma unroll
            for (int i = 0; i < 32; i++)
                vr[i] = V[(kn + vh * 32 + i) * HD + vc];
        }

        // ---- O += P @ V : warp m16 x n128, 4 k16-chunks ----
        #pragma unroll
        for (int k = 0; k < 4; k++) {
            uint2 pa = *(const uint2*)&Ps[(mw + g)     * LDP + k * 8 + 2 * c4];
            uint2 pb = *(const uint2*)&Ps[(mw + g + 8) * LDP + k * 8 + 2 * c4];
            #pragma unroll
            for (int t = 0; t < 16; t++) {
                uint2 vb = *(const uint2*)&Vq[(k * 4 + c4) * LDVQ + 2 * (t * 8 + g)];
                mma_f16(of[t], pa.x, pb.x, pa.y, pb.y, vb.x, vb.y);
            }
        }

        __syncthreads();   // all warps done reading Vq (and orders Ks stores)

        // ---- store prefetched V ----
        if (more) {
            #pragma unroll
            for (int ci = 0; ci < 2; ci++) {
                int ch = 2 * vh + ci;
                #pragma unroll
                for (int i = 0; i < 4; i++) {
                    *(uint2*)&Vq[(ch * 4 + i) * LDVQ + 2 * vc] =
                        make_uint2(f2h2(vr[ci*16 + 2*i],     vr[ci*16 + 2*i + 1]),
                                   f2h2(vr[ci*16 + 2*i + 8], vr[ci*16 + 2*i + 9]));
                }
            }
        }
    }

    // ---- epilogue ----
    const float inv0 = 1.0f / l0;
    const float inv1 = 1.0f / l1;
    const int r0 = q0 + mw + g;
    const int r1 = r0 + 8;
    #pragma unroll
    for (int t = 0; t < 16; t++) {
        const int col = t * 8 + c4 * 2;
        *(float2*)&O[r0 * HD + col] = make_float2(of[t][0] * inv0, of[t][1] * inv0);
        *(float2*)&O[r1 * HD + col] = make_float2(of[t][2] * inv1, of[t][3] * inv1);
    }
}

// ---------------------------------------------------------------------------
// Launch
// ---------------------------------------------------------------------------
extern "C" void kernel_launch(void* const* d_in, const int* in_sizes, int n_in,
                              void* d_out, int out_size)
{
    const float* x    = (const float*)d_in[0];  // [4,2048,128]
    const float* qkv  = (const float*)d_in[1];  // [128, 3072]
    const float* proj = (const float*)d_in[2];  // [1024, 128]
    float* out = (float*)d_out;                 // [4,2048,128]

    float *gq, *gk, *gv, *go;
    cudaGetSymbolAddress((void**)&gq, g_q);
    cudaGetSymbolAddress((void**)&gk, g_k);
    cudaGetSymbolAddress((void**)&gv, g_v);
    cudaGetSymbolAddress((void**)&go, g_o);

    const int M = HB * SEQ;          // 8192
    const int NQKV = NH * HD;        // 1024

    // Fused QKV: [8192,128] @ [128,3072], BN=64 tiles, split epilogue
    const int gemm_smem = (128 * GA_LD + 32 * GB_LD) * (int)sizeof(uint32_t); // 52,224
    cudaFuncSetAttribute(f16_gemm_kernel<1>,
                         cudaFuncAttributeMaxDynamicSharedMemorySize, gemm_smem);
    f16_gemm_kernel<1><<<dim3(3 * NQKV / 64, M / 128), 256, gemm_smem>>>(
        x, HD, qkv, 3 * NQKV, gq, gk, gv, NQKV, NQKV);

    // Flash attention: 32 heads x 16 q-tiles, 256 threads
    const int flash_smem = SMEM_WORDS * (int)sizeof(uint32_t);  // 87,552 B
    cudaFuncSetAttribute(flash_f16_kernel,
                         cudaFuncAttributeMaxDynamicSharedMemorySize, flash_smem);
    flash_f16_kernel<<<dim3(HEADS, SEQ / BQ), 256, flash_smem>>>(gq, gk, gv, go);

    // Projection: [8192,1024] @ [1024,128], 8 k-iterations
    cudaFuncSetAttribute(f16_gemm_kernel<8>,
                         cudaFuncAttributeMaxDynamicSharedMemorySize, gemm_smem);
    f16_gemm_kernel<8><<<dim3(HD / 64, M / 128), 256, gemm_smem>>>(
        go, NQKV, proj, HD, out, out, out, HD, 1 << 30);
}

// round 11
// speedup vs baseline: 2.2197x; 1.7450x over previous
#include <cuda_runtime.h>
#include <cuda_fp16.h>
#include <math.h>
#include <stdint.h>

// Problem constants (B=4, S=2048, H=128, NH=8)
#define HB 4
#define SEQ 2048
#define HD 128
#define NH 8
#define HEADS (HB * NH)              // 32
#define HEADELEMS (SEQ * HD)         // 262144
#define YELEMS (HB * SEQ * NH * HD)  // 8388608

// fp16 staging buffers (uint32 = half2 words). Allocation-free device globals.
__device__ uint32_t g_xh[8192 * 64];          // x, chunk-interleaved rows
__device__ uint32_t g_wh[24 * 32 * 256];      // qkv weights, row-pair per 128-col block
__device__ uint32_t g_ph[8 * 32 * 256];       // proj weights, row-pair per 128-row block
__device__ uint32_t g_qh[HEADS * 2048 * 64];  // Q, head-chunk interleaved rows (pre-scaled)
__device__ uint32_t g_kh[HEADS * 2048 * 64];  // K, same layout
__device__ float    g_v [YELEMS];             // V fp32 (GEMM output)
__device__ uint32_t g_vh[HEADS * 32 * 16 * 256]; // V row-pair per 64-row block
__device__ uint32_t g_oh[8192 * 512];         // O, interleaved rows (1024 halfs)

__device__ __forceinline__ uint32_t f2h2(float lo, float hi) {
    __half2 h = __floats2half2_rn(lo, hi);
    return *reinterpret_cast<uint32_t*>(&h);
}

__device__ __forceinline__ void mma_f16(float c[4],
    uint32_t a0, uint32_t a1, uint32_t a2, uint32_t a3,
    uint32_t b0, uint32_t b1)
{
    asm volatile(
        "mma.sync.aligned.m16n8k16.row.col.f32.f16.f16.f32 "
        "{%0,%1,%2,%3}, {%4,%5,%6,%7}, {%8,%9}, {%0,%1,%2,%3};\n"
        : "+f"(c[0]), "+f"(c[1]), "+f"(c[2]), "+f"(c[3])
        : "r"(a0), "r"(a1), "r"(a2), "r"(a3), "r"(b0), "r"(b1));
}

// 16 consecutive floats -> 8 half2 words stored [w0,w4,w1,w5,w2,w6,w3,w7];
// uint2 read at word 2*c4 yields {w[c4], w[c4+4]} = the fp16 A-fragment pair.
#define STORE_CHUNK(dst, A, B_, C_, D_)                                         \
    do {                                                                        \
        ((uint4*)(dst))[0] = make_uint4(f2h2((A).x,(A).y),  f2h2((C_).x,(C_).y),\
                                        f2h2((A).z,(A).w),  f2h2((C_).z,(C_).w));\
        ((uint4*)(dst))[1] = make_uint4(f2h2((B_).x,(B_).y), f2h2((D_).x,(D_).y),\
                                        f2h2((B_).z,(B_).w), f2h2((D_).z,(D_).w));\
    } while (0)

__device__ __forceinline__ void cp_async16(uint32_t* smem_dst, const uint32_t* gsrc) {
    uint32_t d = (uint32_t)__cvta_generic_to_shared(smem_dst);
    asm volatile("cp.async.cg.shared.global [%0], [%1], 16;\n" :: "r"(d), "l"(gsrc) : "memory");
}
#define CP_COMMIT() asm volatile("cp.async.commit_group;\n" ::: "memory")
#define CP_WAIT0()  asm volatile("cp.async.wait_group 0;\n" ::: "memory")

// ---------------------------------------------------------------------------
// One-time format-conversion kernels
// ---------------------------------------------------------------------------
__global__ void convert_x_kernel(const float* __restrict__ x, uint32_t* __restrict__ xh) {
    int id = blockIdx.x * 256 + threadIdx.x;    // 65536 = 8192 rows x 8 chunks
    int r = id >> 3, ch = id & 7;
    const float* src = &x[r * 128 + ch * 16];
    float4 a = *(const float4*)src;
    float4 b = *(const float4*)(src + 4);
    float4 c = *(const float4*)(src + 8);
    float4 d = *(const float4*)(src + 12);
    STORE_CHUNK(&xh[r * 64 + ch * 8], a, b, c, d);
}

// qkv [128,3072] -> row-pair blocks per 128-col block; Q block scaled by 1/sqrt(128)
__global__ void convert_w_kernel(const float* __restrict__ w, uint32_t* __restrict__ wh) {
    int id = blockIdx.x * 256 + threadIdx.x;    // 98304
    int n  = id & 127;
    int vr = (id >> 7) & 31;
    int cb = id >> 12;                          // 0..23
    int ch = vr >> 2, i = vr & 3;
    int r0 = ch * 16 + 2 * i;
    float s = (cb < 8) ? 0.08838834764831845f : 1.0f;  // fold QK scale into Wq
    int col = cb * 128 + n;
    float v0 = w[(r0    ) * 3072 + col] * s;
    float v1 = w[(r0 + 1) * 3072 + col] * s;
    float v2 = w[(r0 + 8) * 3072 + col] * s;
    float v3 = w[(r0 + 9) * 3072 + col] * s;
    *(uint2*)&wh[cb * 8192 + vr * 256 + 2 * n] = make_uint2(f2h2(v0, v1), f2h2(v2, v3));
}

// proj [1024,128] -> row-pair blocks per 128-row (K) block
__global__ void convert_p_kernel(const float* __restrict__ w, uint32_t* __restrict__ ph) {
    int id = blockIdx.x * 256 + threadIdx.x;    // 32768
    int n  = id & 127;
    int vr = (id >> 7) & 31;
    int kb = id >> 12;                          // 0..7
    int ch = vr >> 2, i = vr & 3;
    int r0 = kb * 128 + ch * 16 + 2 * i;
    float v0 = w[(r0    ) * 128 + n];
    float v1 = w[(r0 + 1) * 128 + n];
    float v2 = w[(r0 + 8) * 128 + n];
    float v3 = w[(r0 + 9) * 128 + n];
    *(uint2*)&ph[kb * 8192 + vr * 256 + 2 * n] = make_uint2(f2h2(v0, v1), f2h2(v2, v3));
}

// g_v fp32 (flat head-chunks [2048,128]) -> row-pair per 64-row block
__global__ void convert_v_kernel(const float* __restrict__ v, uint32_t* __restrict__ vh) {
    int id = blockIdx.x * 256 + threadIdx.x;    // 2,097,152
    int fc = id & 127;
    int vr = (id >> 7) & 15;
    int bb = (id >> 11) & 31;
    int hb = id >> 16;
    int ch = vr >> 2, i = vr & 3;
    int lr0 = ch * 16 + 2 * i;
    long base = (long)hb * 262144 + (bb * 64 + lr0) * 128 + fc;
    float v0 = v[base];
    float v1 = v[base + 128];
    float v2 = v[base + 1024];
    float v3 = v[base + 1152];
    *(uint2*)&vh[hb * 131072 + bb * 4096 + vr * 256 + 2 * fc] =
        make_uint2(f2h2(v0, v1), f2h2(v2, v3));
}

// ---------------------------------------------------------------------------
// cp.async-fed fp16 GEMM: C = A[M,K] @ B[K,N], BM=128, BN=128, BK=128/iter.
// A: pre-interleaved fp16 rows (lda_w words/row). B: row-pair blocks (8192 w).
// Block offset = (bx + kt)*8192: QKV has NKITER=1 (block=bx), proj bx=0 (block=kt).
// EPI=1: QKV routing (segs 0/1 -> fp16 head-chunk layout, seg 2 -> fp32 g_v).
// EPI=0: fp32 [M,128] output. smem 70,656 B -> 2 CTAs/SM.
// ---------------------------------------------------------------------------
template<int NKITER, int EPI>
__global__ __launch_bounds__(256, 2)
void f16_gemm_cp(const uint32_t* __restrict__ A, int lda_w,
                 const uint32_t* __restrict__ Bq,
                 uint32_t* __restrict__ H0, uint32_t* __restrict__ H1,
                 float* __restrict__ Cf)
{
    extern __shared__ uint32_t smg[];
    uint32_t* As = smg;                 // 128 x 72
    uint32_t* Bs = smg + 128 * 72;      // 32 x 264

    const int tid  = threadIdx.x;
    const int lane = tid & 31;
    const int g    = lane >> 2;
    const int c4   = lane & 3;
    const int mw   = (tid >> 5) * 16;
    const int bx   = blockIdx.x;
    const int row0 = blockIdx.y * 128;

    float acc[16][4];
    #pragma unroll
    for (int t = 0; t < 16; t++)
        #pragma unroll
        for (int j = 0; j < 4; j++) acc[t][j] = 0.0f;

    for (int kt = 0; kt < NKITER; kt++) {
        #pragma unroll
        for (int p = 0; p < 8; p++) {
            int cid = p * 256 + tid;
            int r = cid >> 4, w4 = cid & 15;
            cp_async16(&As[r * 72 + w4 * 4],
                       A + (long)(row0 + r) * lda_w + kt * 64 + w4 * 4);
        }
        #pragma unroll
        for (int p = 0; p < 8; p++) {
            int cid = p * 256 + tid;
            int vr = cid >> 6, w = cid & 63;
            cp_async16(&Bs[vr * 264 + w * 4],
                       Bq + (bx + kt) * 8192 + vr * 256 + w * 4);
        }
        CP_COMMIT(); CP_WAIT0();
        __syncthreads();

        #pragma unroll
        for (int kc = 0; kc < 8; kc++) {
            uint2 aa = *(const uint2*)&As[(mw + g)     * 72 + kc * 8 + 2 * c4];
            uint2 ab = *(const uint2*)&As[(mw + g + 8) * 72 + kc * 8 + 2 * c4];
            #pragma unroll
            for (int t = 0; t < 16; t++) {
                uint2 bb = *(const uint2*)&Bs[(kc * 4 + c4) * 264 + 2 * (t * 8 + g)];
                mma_f16(acc[t], aa.x, ab.x, aa.y, ab.y, bb.x, bb.y);
            }
        }
        __syncthreads();
    }

    const int r0 = row0 + mw + g;
    const int r1 = r0 + 8;
    if (EPI == 0) {
        #pragma unroll
        for (int t = 0; t < 16; t++) {
            const int col = t * 8 + 2 * c4;
            *(float2*)&Cf[r0 * 128 + col] = make_float2(acc[t][0], acc[t][1]);
            *(float2*)&Cf[r1 * 128 + col] = make_float2(acc[t][2], acc[t][3]);
        }
    } else {
        const int seg = bx >> 3;
        const int m   = bx & 7;
        if (seg < 2) {
            uint32_t* H = seg ? H1 : H0;
            const int hb = r0 >> 8;
            const int t0 = (r0 & 255) * 8 + m;
            const int t1 = (r1 & 255) * 8 + m;
            #pragma unroll
            for (int t = 0; t < 16; t++) {
                const int pos = (t >> 1) * 8 + 2 * c4 + (t & 1);
                H[hb * 131072 + t0 * 64 + pos] = f2h2(acc[t][0], acc[t][1]);
                H[hb * 131072 + t1 * 64 + pos] = f2h2(acc[t][2], acc[t][3]);
            }
        } else {
            #pragma unroll
            for (int t = 0; t < 16; t++) {
                const int col = m * 128 + t * 8 + 2 * c4;
                *(float2*)&Cf[(long)r0 * 1024 + col] = make_float2(acc[t][0], acc[t][1]);
                *(float2*)&Cf[(long)r1 * 1024 + col] = make_float2(acc[t][2], acc[t][3]);
            }
        }
    }
}

// ---------------------------------------------------------------------------
// FP16 flash attention v5: cp.async-fed from pre-formatted gmem, BQ=128,
// 256 threads, 2 CTAs/SM. K single-buffered + V double-buffered pipeline.
// Pads 72/40/264 are all ==8 mod 32 -> conflict-free LDS.64 fragment loads.
// smem = 27,392 words = 109,568 B.
// ---------------------------------------------------------------------------
#define FLDQ 72
#define FLDK 72
#define FLDV 264
#define FLDP 40
#define FQS  0
#define FKS  (128 * FLDQ)            // 9216
#define FVS0 (FKS + 64 * FLDK)       // 13824
#define FVS1 (FVS0 + 16 * FLDV)      // 18048
#define FPS  (FVS1 + 16 * FLDV)      // 22272
#define FSMEMW (FPS + 128 * FLDP)    // 27392

__global__ __launch_bounds__(256, 2)
void flash_f16_kernel(const uint32_t* __restrict__ qh, const uint32_t* __restrict__ kh,
                      const uint32_t* __restrict__ vh, uint32_t* __restrict__ oh)
{
    extern __shared__ uint32_t sm[];
    uint32_t* Qs = sm + FQS;
    uint32_t* Ks = sm + FKS;
    uint32_t* Ps = sm + FPS;

    const int tid  = threadIdx.x;
    const int lane = tid & 31;
    const int g    = lane >> 2;
    const int c4   = lane & 3;
    const int mw   = (tid >> 5) * 16;

    const int hb = blockIdx.x;
    const int qt = (int)gridDim.y - 1 - (int)blockIdx.y;   // big q-tiles first
    const int q0 = qt * 128;

    const uint32_t* QH = qh + hb * 131072;
    const uint32_t* KH = kh + hb * 131072;
    const uint32_t* VH = vh + hb * 131072;

    const int nkv = (q0 + 128) / 64;

    // ---- prologue: Q tile + K0 + V0 via cp.async ----
    #pragma unroll
    for (int p = 0; p < 8; p++) {
        int cid = p * 256 + tid;
        int r = cid >> 4, w4 = cid & 15;
        cp_async16(&Qs[r * FLDQ + w4 * 4], QH + (q0 + r) * 64 + w4 * 4);
    }
    #pragma unroll
    for (int p = 0; p < 4; p++) {
        int cid = p * 256 + tid;
        int r = cid >> 4, w4 = cid & 15;
        cp_async16(&Ks[r * FLDK + w4 * 4], KH + r * 64 + w4 * 4);
    }
    #pragma unroll
    for (int p = 0; p < 4; p++) {
        int cid = p * 256 + tid;
        int vr = cid >> 6, w = cid & 63;
        cp_async16(&sm[FVS0 + vr * FLDV + w * 4], VH + vr * 256 + w * 4);
    }
    CP_COMMIT(); CP_WAIT0();
    __syncthreads();

    float of[16][4];
    #pragma unroll
    for (int t = 0; t < 16; t++)
        #pragma unroll
        for (int j = 0; j < 4; j++) of[t][j] = 0.0f;
    float m0 = -INFINITY, m1 = -INFINITY, l0 = 0.0f, l1 = 0.0f;

    for (int kt = 0; kt < nkv; kt++) {
        const bool more = (kt + 1 < nkv);
        const uint32_t* Vb = sm + ((kt & 1) ? FVS1 : FVS0);

        // ---- S = Qs @ Ks^T : warp m16 x n64, 8 k16-chunks (scale pre-folded) ----
        float sf[8][4];
        #pragma unroll
        for (int t = 0; t < 8; t++)
            #pragma unroll
            for (int j = 0; j < 4; j++) sf[t][j] = 0.0f;

        #pragma unroll
        for (int k = 0; k < 8; k++) {
            uint2 qa = *(const uint2*)&Qs[(mw + g)     * FLDQ + k * 8 + 2 * c4];
            uint2 qb = *(const uint2*)&Qs[(mw + g + 8) * FLDQ + k * 8 + 2 * c4];
            #pragma unroll
            for (int t = 0; t < 8; t++) {
                uint2 kb = *(const uint2*)&Ks[(t * 8 + g) * FLDK + k * 8 + 2 * c4];
                mma_f16(sf[t], qa.x, qb.x, qa.y, qb.y, kb.x, kb.y);
            }
        }

        // ---- causal mask (tiles touching the diagonal) ----
        if (kt >= nkv - 2) {
            const int k0 = kt * 64;
            const int r0 = q0 + mw + g;
            const int r1 = r0 + 8;
            #pragma unroll
            for (int t = 0; t < 8; t++) {
                const int cg0 = k0 + t * 8 + c4 * 2;
                if (cg0     > r0) sf[t][0] = -INFINITY;
                if (cg0 + 1 > r0) sf[t][1] = -INFINITY;
                if (cg0     > r1) sf[t][2] = -INFINITY;
                if (cg0 + 1 > r1) sf[t][3] = -INFINITY;
            }
        }

        __syncthreads();   // all warps done reading Ks

        // ---- prefetch next K (into Ks) and V (into other buffer) ----
        if (more) {
            const int kn = (kt + 1) * 64;
            uint32_t* Vn = sm + (((kt + 1) & 1) ? FVS1 : FVS0);
            #pragma unroll
            for (int p = 0; p < 4; p++) {
                int cid = p * 256 + tid;
                int r = cid >> 4, w4 = cid & 15;
                cp_async16(&Ks[r * FLDK + w4 * 4], KH + (kn + r) * 64 + w4 * 4);
            }
            #pragma unroll
            for (int p = 0; p < 4; p++) {
                int cid = p * 256 + tid;
                int vr = cid >> 6, w = cid & 63;
                cp_async16(&Vn[vr * FLDV + w * 4],
                           VH + (kt + 1) * 4096 + vr * 256 + w * 4);
            }
            CP_COMMIT();
        }

        // ---- online softmax (quad-local reduce) ----
        float mx0 = -INFINITY, mx1 = -INFINITY;
        #pragma unroll
        for (int t = 0; t < 8; t++) {
            mx0 = fmaxf(mx0, fmaxf(sf[t][0], sf[t][1]));
            mx1 = fmaxf(mx1, fmaxf(sf[t][2], sf[t][3]));
        }
        mx0 = fmaxf(mx0, __shfl_xor_sync(0xffffffffu, mx0, 1));
        mx0 = fmaxf(mx0, __shfl_xor_sync(0xffffffffu, mx0, 2));
        mx1 = fmaxf(mx1, __shfl_xor_sync(0xffffffffu, mx1, 1));
        mx1 = fmaxf(mx1, __shfl_xor_sync(0xffffffffu, mx1, 2));

        const float mn0 = fmaxf(m0, mx0);
        const float mn1 = fmaxf(m1, mx1);
        const float al0 = __expf(m0 - mn0);
        const float al1 = __expf(m1 - mn1);

        float s0 = 0.0f, s1 = 0.0f;
        #pragma unroll
        for (int t = 0; t < 8; t++) {
            sf[t][0] = __expf(sf[t][0] - mn0);
            sf[t][1] = __expf(sf[t][1] - mn0);
            sf[t][2] = __expf(sf[t][2] - mn1);
            sf[t][3] = __expf(sf[t][3] - mn1);
            s0 += sf[t][0] + sf[t][1];
            s1 += sf[t][2] + sf[t][3];
        }
        s0 += __shfl_xor_sync(0xffffffffu, s0, 1);
        s0 += __shfl_xor_sync(0xffffffffu, s0, 2);
        s1 += __shfl_xor_sync(0xffffffffu, s1, 1);
        s1 += __shfl_xor_sync(0xffffffffu, s1, 2);

        l0 = l0 * al0 + s0;  m0 = mn0;
        l1 = l1 * al1 + s1;  m1 = mn1;

        #pragma unroll
        for (int t = 0; t < 16; t++) {
            of[t][0] *= al0; of[t][1] *= al0;
            of[t][2] *= al1; of[t][3] *= al1;
        }

        // ---- store P (fp16, interleaved chunk position) ----
        #pragma unroll
        for (int t = 0; t < 8; t++) {
            const int wp = (t >> 1) * 8 + 2 * c4 + (t & 1);
            Ps[(mw + g)     * FLDP + wp] = f2h2(sf[t][0], sf[t][1]);
            Ps[(mw + g + 8) * FLDP + wp] = f2h2(sf[t][2], sf[t][3]);
        }
        __syncwarp();

        // ---- O += P @ V : warp m16 x n128, 4 k16-chunks ----
        #pragma unroll
        for (int k = 0; k < 4; k++) {
            uint2 pa = *(const uint2*)&Ps[(mw + g)     * FLDP + k * 8 + 2 * c4];
            uint2 pb = *(const uint2*)&Ps[(mw + g + 8) * FLDP + k * 8 + 2 * c4];
            #pragma unroll
            for (int t = 0; t < 16; t++) {
                uint2 vb = *(const uint2*)&Vb[(k * 4 + c4) * FLDV + 2 * (t * 8 + g)];
                mma_f16(of[t], pa.x, pb.x, pa.y, pb.y, vb.x, vb.y);
            }
        }

        CP_WAIT0();        // next tile's K/V landed (covered by softmax+PV)
        __syncthreads();
    }

    // ---- epilogue: O /= l, write fp16 interleaved rows of g_oh ----
    const float inv0 = 1.0f / l0;
    const float inv1 = 1.0f / l1;
    const int r0f = q0 + mw + g;
    const int r1f = r0f + 8;
    const int grow0 = hb * 256 + (r0f >> 3);
    const int grow1 = hb * 256 + (r1f >> 3);
    const int cb0 = (r0f & 7) * 8;
    const int cb1 = (r1f & 7) * 8;
    #pragma unroll
    for (int t = 0; t < 16; t++) {
        const int sub = 2 * c4 + (t & 1);
        oh[grow0 * 512 + (cb0 + (t >> 1)) * 8 + sub] = f2h2(of[t][0] * inv0, of[t][1] * inv0);
        oh[grow1 * 512 + (cb1 + (t >> 1)) * 8 + sub] = f2h2(of[t][2] * inv1, of[t][3] * inv1);
    }
}

// ---------------------------------------------------------------------------
// Launch
// ---------------------------------------------------------------------------
extern "C" void kernel_launch(void* const* d_in, const int* in_sizes, int n_in,
                              void* d_out, int out_size)
{
    const float* x    = (const float*)d_in[0];  // [4,2048,128]
    const float* qkv  = (const float*)d_in[1];  // [128, 3072]
    const float* proj = (const float*)d_in[2];  // [1024, 128]
    float* out = (float*)d_out;                 // [4,2048,128]

    uint32_t *xh, *wh, *ph, *qh, *kh, *vh, *oh;
    float *vf;
    cudaGetSymbolAddress((void**)&xh, g_xh);
    cudaGetSymbolAddress((void**)&wh, g_wh);
    cudaGetSymbolAddress((void**)&ph, g_ph);
    cudaGetSymbolAddress((void**)&qh, g_qh);
    cudaGetSymbolAddress((void**)&kh, g_kh);
    cudaGetSymbolAddress((void**)&vf, g_v);
    cudaGetSymbolAddress((void**)&vh, g_vh);
    cudaGetSymbolAddress((void**)&oh, g_oh);

    // format conversions (independent)
    convert_x_kernel<<<256, 256>>>(x, xh);
    convert_w_kernel<<<384, 256>>>(qkv, wh);
    convert_p_kernel<<<128, 256>>>(proj, ph);

    const int gemm_smem = (128 * 72 + 32 * 264) * (int)sizeof(uint32_t);  // 70,656
    cudaFuncSetAttribute(f16_gemm_cp<1, 1>,
                         cudaFuncAttributeMaxDynamicSharedMemorySize, gemm_smem);
    f16_gemm_cp<1, 1><<<dim3(24, 64), 256, gemm_smem>>>(xh, 64, wh, qh, kh, vf);

    convert_v_kernel<<<8192, 256>>>(vf, vh);

    const int flash_smem = FSMEMW * (int)sizeof(uint32_t);  // 109,568
    cudaFuncSetAttribute(flash_f16_kernel,
                         cudaFuncAttributeMaxDynamicSharedMemorySize, flash_smem);
    flash_f16_kernel<<<dim3(HEADS, SEQ / 128), 256, flash_smem>>>(qh, kh, vh, oh);

    cudaFuncSetAttribute(f16_gemm_cp<8, 0>,
                         cudaFuncAttributeMaxDynamicSharedMemorySize, gemm_smem);
    f16_gemm_cp<8, 0><<<dim3(1, 64), 256, gemm_smem>>>(oh, 512, ph, nullptr, nullptr, out);
}

// round 12
// speedup vs baseline: 2.3366x; 1.0526x over previous
#include <cuda_runtime.h>
#include <cuda_fp16.h>
#include <math.h>
#include <stdint.h>

// Problem constants (B=4, S=2048, H=128, NH=8)
#define HB 4
#define SEQ 2048
#define HD 128
#define NH 8
#define HEADS (HB * NH)              // 32
#define HEADELEMS (SEQ * HD)         // 262144

// fp16 staging buffers (uint32 = half2 words). Allocation-free device globals.
__device__ uint32_t g_xh[8192 * 64];          // x, chunk-interleaved rows
__device__ uint32_t g_wh[24 * 32 * 256];      // qkv weights, row-pair per 128-col block
__device__ uint32_t g_ph[8 * 32 * 256];       // proj weights, row-pair per 128-row block
__device__ uint32_t g_qh[HEADS * 2048 * 64];  // Q, head-chunk interleaved rows (pre-scaled)
__device__ uint32_t g_kh[HEADS * 2048 * 64];  // K, same layout
__device__ uint32_t g_vp[HEADS * 2048 * 64];  // V plain fp16 rows (64 words/row)
__device__ uint32_t g_vh[HEADS * 32 * 16 * 256]; // V row-pair per 64-row block
__device__ uint32_t g_oh[8192 * 512];         // O, interleaved rows (1024 halfs)

__device__ __forceinline__ uint32_t f2h2(float lo, float hi) {
    __half2 h = __floats2half2_rn(lo, hi);
    return *reinterpret_cast<uint32_t*>(&h);
}

__device__ __forceinline__ void mma_f16(float c[4],
    uint32_t a0, uint32_t a1, uint32_t a2, uint32_t a3,
    uint32_t b0, uint32_t b1)
{
    asm volatile(
        "mma.sync.aligned.m16n8k16.row.col.f32.f16.f16.f32 "
        "{%0,%1,%2,%3}, {%4,%5,%6,%7}, {%8,%9}, {%0,%1,%2,%3};\n"
        : "+f"(c[0]), "+f"(c[1]), "+f"(c[2]), "+f"(c[3])
        : "r"(a0), "r"(a1), "r"(a2), "r"(a3), "r"(b0), "r"(b1));
}

// 16 consecutive floats -> 8 half2 words stored [w0,w4,w1,w5,w2,w6,w3,w7];
// uint2 read at word 2*c4 yields {w[c4], w[c4+4]} = the fp16 A-fragment pair.
#define STORE_CHUNK(dst, A, B_, C_, D_)                                         \
    do {                                                                        \
        ((uint4*)(dst))[0] = make_uint4(f2h2((A).x,(A).y),  f2h2((C_).x,(C_).y),\
                                        f2h2((A).z,(A).w),  f2h2((C_).z,(C_).w));\
        ((uint4*)(dst))[1] = make_uint4(f2h2((B_).x,(B_).y), f2h2((D_).x,(D_).y),\
                                        f2h2((B_).z,(B_).w), f2h2((D_).z,(D_).w));\
    } while (0)

__device__ __forceinline__ void cp_async16(uint32_t* smem_dst, const uint32_t* gsrc) {
    uint32_t d = (uint32_t)__cvta_generic_to_shared(smem_dst);
    asm volatile("cp.async.cg.shared.global [%0], [%1], 16;\n" :: "r"(d), "l"(gsrc) : "memory");
}
#define CP_COMMIT() asm volatile("cp.async.commit_group;\n" ::: "memory")
#define CP_WAIT0()  asm volatile("cp.async.wait_group 0;\n" ::: "memory")
#define CP_WAIT1()  asm volatile("cp.async.wait_group 1;\n" ::: "memory")

// ---------------------------------------------------------------------------
// One-time format-conversion kernels
// ---------------------------------------------------------------------------
__global__ void convert_x_kernel(const float* __restrict__ x, uint32_t* __restrict__ xh) {
    int id = blockIdx.x * 256 + threadIdx.x;    // 65536 = 8192 rows x 8 chunks
    int r = id >> 3, ch = id & 7;
    const float* src = &x[r * 128 + ch * 16];
    float4 a = *(const float4*)src;
    float4 b = *(const float4*)(src + 4);
    float4 c = *(const float4*)(src + 8);
    float4 d = *(const float4*)(src + 12);
    STORE_CHUNK(&xh[r * 64 + ch * 8], a, b, c, d);
}

// qkv [128,3072] -> row-pair blocks per 128-col block; Q block scaled by 1/sqrt(128)
__global__ void convert_w_kernel(const float* __restrict__ w, uint32_t* __restrict__ wh) {
    int id = blockIdx.x * 256 + threadIdx.x;    // 98304
    int n  = id & 127;
    int vr = (id >> 7) & 31;
    int cb = id >> 12;                          // 0..23
    int ch = vr >> 2, i = vr & 3;
    int r0 = ch * 16 + 2 * i;
    float s = (cb < 8) ? 0.08838834764831845f : 1.0f;  // fold QK scale into Wq
    int col = cb * 128 + n;
    float v0 = w[(r0    ) * 3072 + col] * s;
    float v1 = w[(r0 + 1) * 3072 + col] * s;
    float v2 = w[(r0 + 8) * 3072 + col] * s;
    float v3 = w[(r0 + 9) * 3072 + col] * s;
    *(uint2*)&wh[cb * 8192 + vr * 256 + 2 * n] = make_uint2(f2h2(v0, v1), f2h2(v2, v3));
}

// proj [1024,128] -> row-pair blocks per 128-row (K) block
__global__ void convert_p_kernel(const float* __restrict__ w, uint32_t* __restrict__ ph) {
    int id = blockIdx.x * 256 + threadIdx.x;    // 32768
    int n  = id & 127;
    int vr = (id >> 7) & 31;
    int kb = id >> 12;                          // 0..7
    int ch = vr >> 2, i = vr & 3;
    int r0 = kb * 128 + ch * 16 + 2 * i;
    float v0 = w[(r0    ) * 128 + n];
    float v1 = w[(r0 + 1) * 128 + n];
    float v2 = w[(r0 + 8) * 128 + n];
    float v3 = w[(r0 + 9) * 128 + n];
    *(uint2*)&ph[kb * 8192 + vr * 256 + 2 * n] = make_uint2(f2h2(v0, v1), f2h2(v2, v3));
}

// plain fp16 V rows -> row-pair per 64-row block (coalesced half repack)
__global__ void convert_v_kernel(const uint32_t* __restrict__ vp, uint32_t* __restrict__ vh) {
    int id = blockIdx.x * 256 + threadIdx.x;    // 1,048,576
    int fc2 = id & 63;                          // word within row (2 cols)
    int vr  = (id >> 6) & 15;
    int bb  = (id >> 10) & 31;
    int hb  = id >> 15;
    int ch = vr >> 2, i = vr & 3;
    int R = bb * 64 + ch * 16 + 2 * i;
    const uint32_t* base = vp + hb * 131072 + R * 64 + fc2;
    uint32_t a = base[0];
    uint32_t b = base[64];
    uint32_t c = base[512];
    uint32_t d = base[576];
    uint4 o;
    o.x = __byte_perm(a, b, 0x5410);   // h2(V[R][fc],   V[R+1][fc])
    o.y = __byte_perm(c, d, 0x5410);   // h2(V[R+8][fc], V[R+9][fc])
    o.z = __byte_perm(a, b, 0x7632);   // fc+1 versions
    o.w = __byte_perm(c, d, 0x7632);
    *(uint4*)&vh[hb * 131072 + bb * 4096 + vr * 256 + 4 * fc2] = o;
}

// ---------------------------------------------------------------------------
// Fused QKV GEMM v3: x[8192,128] @ W[128,3072]. Each CTA: one 128-col block,
// FOUR 128-row tiles (B loaded once, A double-buffered via cp.async groups).
// grid (24,16), 256 thr, 2 CTAs/SM (smem 107,520 B).
// Epilogue: Q/K -> head-chunk interleaved fp16 (scale pre-folded into Wq);
// V -> plain fp16 rows of g_vp.
// ---------------------------------------------------------------------------
__global__ __launch_bounds__(256, 2)
void f16_gemm_qkv(const uint32_t* __restrict__ A, const uint32_t* __restrict__ Bq,
                  uint32_t* __restrict__ H0, uint32_t* __restrict__ H1,
                  uint32_t* __restrict__ Vp)
{
    extern __shared__ uint32_t smg[];
    uint32_t* As0 = smg;                 // 128 x 72
    uint32_t* As1 = smg + 9216;          // 128 x 72
    uint32_t* Bs  = smg + 18432;         // 32 x 264

    const int tid  = threadIdx.x;
    const int lane = tid & 31;
    const int g    = lane >> 2;
    const int c4   = lane & 3;
    const int mw   = (tid >> 5) * 16;
    const int bx   = blockIdx.x;         // 0..23
    const int byr  = blockIdx.y;         // 0..15
    const int seg  = bx >> 3;
    const int m    = bx & 7;

    // prologue: B + A0 (group0), A1 (group1)
    #pragma unroll
    for (int p = 0; p < 8; p++) {
        int cid = p * 256 + tid;
        int vr = cid >> 6, w = cid & 63;
        cp_async16(&Bs[vr * 264 + w * 4], Bq + bx * 8192 + vr * 256 + w * 4);
    }
    #pragma unroll
    for (int p = 0; p < 8; p++) {
        int cid = p * 256 + tid;
        int r = cid >> 4, w4 = cid & 15;
        cp_async16(&As0[r * 72 + w4 * 4], A + (byr * 512 + r) * 64 + w4 * 4);
    }
    CP_COMMIT();
    #pragma unroll
    for (int p = 0; p < 8; p++) {
        int cid = p * 256 + tid;
        int r = cid >> 4, w4 = cid & 15;
        cp_async16(&As1[r * 72 + w4 * 4], A + (byr * 512 + 128 + r) * 64 + w4 * 4);
    }
    CP_COMMIT();

    #pragma unroll
    for (int it = 0; it < 4; it++) {
        CP_WAIT1();                     // A[it] (+B at it=0) landed
        __syncthreads();
        const uint32_t* Asb = (it & 1) ? As1 : As0;

        float acc[16][4];
        #pragma unroll
        for (int t = 0; t < 16; t++)
            #pragma unroll
            for (int j = 0; j < 4; j++) acc[t][j] = 0.0f;

        #pragma unroll
        for (int kc = 0; kc < 8; kc++) {
            uint2 aa = *(const uint2*)&Asb[(mw + g)     * 72 + kc * 8 + 2 * c4];
            uint2 ab = *(const uint2*)&Asb[(mw + g + 8) * 72 + kc * 8 + 2 * c4];
            #pragma unroll
            for (int t = 0; t < 16; t++) {
                uint2 bb = *(const uint2*)&Bs[(kc * 4 + c4) * 264 + 2 * (t * 8 + g)];
                mma_f16(acc[t], aa.x, ab.x, aa.y, ab.y, bb.x, bb.y);
            }
        }
        __syncthreads();                // all done reading Asb before refill

        // refill slot: A[it+2] into the buffer just freed (always commit)
        if (it + 2 < 4) {
            uint32_t* Asn = (it & 1) ? As1 : As0;
            #pragma unroll
            for (int p = 0; p < 8; p++) {
                int cid = p * 256 + tid;
                int r = cid >> 4, w4 = cid & 15;
                cp_async16(&Asn[r * 72 + w4 * 4],
                           A + (byr * 512 + (it + 2) * 128 + r) * 64 + w4 * 4);
            }
        }
        CP_COMMIT();

        // epilogue for tile it
        const int r0 = byr * 512 + it * 128 + mw + g;
        const int r1 = r0 + 8;
        if (seg < 2) {
            uint32_t* H = seg ? H1 : H0;
            const int hb = r0 >> 8;
            const int t0 = (r0 & 255) * 8 + m;
            const int t1 = (r1 & 255) * 8 + m;
            #pragma unroll
            for (int t = 0; t < 16; t++) {
                const int pos = (t >> 1) * 8 + 2 * c4 + (t & 1);
                H[hb * 131072 + t0 * 64 + pos] = f2h2(acc[t][0], acc[t][1]);
                H[hb * 131072 + t1 * 64 + pos] = f2h2(acc[t][2], acc[t][3]);
            }
        } else {
            const int hb = r0 >> 8;
            const int s0 = (r0 & 255) * 8 + m;
            const int s1 = (r1 & 255) * 8 + m;
            uint32_t* VPb = Vp + hb * 131072;
            #pragma unroll
            for (int t = 0; t < 16; t++) {
                VPb[s0 * 64 + t * 4 + c4] = f2h2(acc[t][0], acc[t][1]);
                VPb[s1 * 64 + t * 4 + c4] = f2h2(acc[t][2], acc[t][3]);
            }
        }
    }
}

// ---------------------------------------------------------------------------
// Projection GEMM v2: O[8192,1024] @ P[1024,128]. BN=64 (grid 2 x 64),
// double-buffered k-pipeline over 8 iters. smem 108,544 B -> 2 CTAs/SM.
// ---------------------------------------------------------------------------
__global__ __launch_bounds__(256, 2)
void f16_gemm_proj(const uint32_t* __restrict__ A, const uint32_t* __restrict__ Bq,
                   float* __restrict__ Cf)
{
    extern __shared__ uint32_t smg[];
    uint32_t* AsB[2] = { smg, smg + 9216 };                 // each 128 x 72
    uint32_t* BsB[2] = { smg + 18432, smg + 18432 + 4352 }; // each 32 x 136

    const int tid  = threadIdx.x;
    const int lane = tid & 31;
    const int g    = lane >> 2;
    const int c4   = lane & 3;
    const int mw   = (tid >> 5) * 16;
    const int bx   = blockIdx.x;          // 0..1
    const int row0 = blockIdx.y * 128;

    auto loadA = [&](uint32_t* dst, int kt) {
        #pragma unroll
        for (int p = 0; p < 8; p++) {
            int cid = p * 256 + tid;
            int r = cid >> 4, w4 = cid & 15;
            cp_async16(&dst[r * 72 + w4 * 4],
                       A + (long)(row0 + r) * 512 + kt * 64 + w4 * 4);
        }
    };
    auto loadB = [&](uint32_t* dst, int kt) {
        #pragma unroll
        for (int p = 0; p < 4; p++) {
            int cid = p * 256 + tid;
            int vr = cid >> 5, w = cid & 31;
            cp_async16(&dst[vr * 136 + w * 4],
                       Bq + kt * 8192 + vr * 256 + bx * 128 + w * 4);
        }
    };

    loadA(AsB[0], 0); loadB(BsB[0], 0); CP_COMMIT();
    loadA(AsB[1], 1); loadB(BsB[1], 1); CP_COMMIT();

    float acc[8][4];
    #pragma unroll
    for (int t = 0; t < 8; t++)
        #pragma unroll
        for (int j = 0; j < 4; j++) acc[t][j] = 0.0f;

    #pragma unroll
    for (int kt = 0; kt < 8; kt++) {
        CP_WAIT1();
        __syncthreads();
        const uint32_t* As = AsB[kt & 1];
        const uint32_t* Bs = BsB[kt & 1];

        #pragma unroll
        for (int kc = 0; kc < 8; kc++) {
            uint2 aa = *(const uint2*)&As[(mw + g)     * 72 + kc * 8 + 2 * c4];
            uint2 ab = *(const uint2*)&As[(mw + g + 8) * 72 + kc * 8 + 2 * c4];
            #pragma unroll
            for (int t = 0; t < 8; t++) {
                uint2 bb = *(const uint2*)&Bs[(kc * 4 + c4) * 136 + 2 * (t * 8 + g)];
                mma_f16(acc[t], aa.x, ab.x, aa.y, ab.y, bb.x, bb.y);
            }
        }
        __syncthreads();

        if (kt + 2 < 8) { loadA(AsB[kt & 1], kt + 2); loadB(BsB[kt & 1], kt + 2); }
        CP_COMMIT();
    }

    const int r0 = row0 + mw + g;
    const int r1 = r0 + 8;
    #pragma unroll
    for (int t = 0; t < 8; t++) {
        const int col = bx * 64 + t * 8 + 2 * c4;
        *(float2*)&Cf[r0 * 128 + col] = make_float2(acc[t][0], acc[t][1]);
        *(float2*)&Cf[r1 * 128 + col] = make_float2(acc[t][2], acc[t][3]);
    }
}

// ---------------------------------------------------------------------------
// FP16 flash attention v5 (unchanged from round 11): cp.async-fed, BQ=128,
// 256 threads, 2 CTAs/SM, K single- + V double-buffered pipeline.
// ---------------------------------------------------------------------------
#define FLDQ 72
#define FLDK 72
#define FLDV 264
#define FLDP 40
#define FQS  0
#define FKS  (128 * FLDQ)
#define FVS0 (FKS + 64 * FLDK)
#define FVS1 (FVS0 + 16 * FLDV)
#define FPS  (FVS1 + 16 * FLDV)
#define FSMEMW (FPS + 128 * FLDP)

__global__ __launch_bounds__(256, 2)
void flash_f16_kernel(const uint32_t* __restrict__ qh, const uint32_t* __restrict__ kh,
                      const uint32_t* __restrict__ vh, uint32_t* __restrict__ oh)
{
    extern __shared__ uint32_t sm[];
    uint32_t* Qs = sm + FQS;
    uint32_t* Ks = sm + FKS;
    uint32_t* Ps = sm + FPS;

    const int tid  = threadIdx.x;
    const int lane = tid & 31;
    const int g    = lane >> 2;
    const int c4   = lane & 3;
    const int mw   = (tid >> 5) * 16;

    const int hb = blockIdx.x;
    const int qt = (int)gridDim.y - 1 - (int)blockIdx.y;
    const int q0 = qt * 128;

    const uint32_t* QH = qh + hb * 131072;
    const uint32_t* KH = kh + hb * 131072;
    const uint32_t* VH = vh + hb * 131072;

    const int nkv = (q0 + 128) / 64;

    #pragma unroll
    for (int p = 0; p < 8; p++) {
        int cid = p * 256 + tid;
        int r = cid >> 4, w4 = cid & 15;
        cp_async16(&Qs[r * FLDQ + w4 * 4], QH + (q0 + r) * 64 + w4 * 4);
    }
    #pragma unroll
    for (int p = 0; p < 4; p++) {
        int cid = p * 256 + tid;
        int r = cid >> 4, w4 = cid & 15;
        cp_async16(&Ks[r * FLDK + w4 * 4], KH + r * 64 + w4 * 4);
    }
    #pragma unroll
    for (int p = 0; p < 4; p++) {
        int cid = p * 256 + tid;
        int vr = cid >> 6, w = cid & 63;
        cp_async16(&sm[FVS0 + vr * FLDV + w * 4], VH + vr * 256 + w * 4);
    }
    CP_COMMIT(); CP_WAIT0();
    __syncthreads();

    float of[16][4];
    #pragma unroll
    for (int t = 0; t < 16; t++)
        #pragma unroll
        for (int j = 0; j < 4; j++) of[t][j] = 0.0f;
    float m0 = -INFINITY, m1 = -INFINITY, l0 = 0.0f, l1 = 0.0f;

    for (int kt = 0; kt < nkv; kt++) {
        const bool more = (kt + 1 < nkv);
        const uint32_t* Vb = sm + ((kt & 1) ? FVS1 : FVS0);

        float sf[8][4];
        #pragma unroll
        for (int t = 0; t < 8; t++)
            #pragma unroll
            for (int j = 0; j < 4; j++) sf[t][j] = 0.0f;

        #pragma unroll
        for (int k = 0; k < 8; k++) {
            uint2 qa = *(const uint2*)&Qs[(mw + g)     * FLDQ + k * 8 + 2 * c4];
            uint2 qb = *(const uint2*)&Qs[(mw + g + 8) * FLDQ + k * 8 + 2 * c4];
            #pragma unroll
            for (int t = 0; t < 8; t++) {
                uint2 kb = *(const uint2*)&Ks[(t * 8 + g) * FLDK + k * 8 + 2 * c4];
                mma_f16(sf[t], qa.x, qb.x, qa.y, qb.y, kb.x, kb.y);
            }
        }

        if (kt >= nkv - 2) {
            const int k0 = kt * 64;
            const int r0 = q0 + mw + g;
            const int r1 = r0 + 8;
            #pragma unroll
            for (int t = 0; t < 8; t++) {
                const int cg0 = k0 + t * 8 + c4 * 2;
                if (cg0     > r0) sf[t][0] = -INFINITY;
                if (cg0 + 1 > r0) sf[t][1] = -INFINITY;
                if (cg0     > r1) sf[t][2] = -INFINITY;
                if (cg0 + 1 > r1) sf[t][3] = -INFINITY;
            }
        }

        __syncthreads();

        if (more) {
            const int kn = (kt + 1) * 64;
            uint32_t* Vn = sm + (((kt + 1) & 1) ? FVS1 : FVS0);
            #pragma unroll
            for (int p = 0; p < 4; p++) {
                int cid = p * 256 + tid;
                int r = cid >> 4, w4 = cid & 15;
                cp_async16(&Ks[r * FLDK + w4 * 4], KH + (kn + r) * 64 + w4 * 4);
            }
            #pragma unroll
            for (int p = 0; p < 4; p++) {
                int cid = p * 256 + tid;
                int vr = cid >> 6, w = cid & 63;
                cp_async16(&Vn[vr * FLDV + w * 4],
                           VH + (kt + 1) * 4096 + vr * 256 + w * 4);
            }
            CP_COMMIT();
        }

        float mx0 = -INFINITY, mx1 = -INFINITY;
        #pragma unroll
        for (int t = 0; t < 8; t++) {
            mx0 = fmaxf(mx0, fmaxf(sf[t][0], sf[t][1]));
            mx1 = fmaxf(mx1, fmaxf(sf[t][2], sf[t][3]));
        }
        mx0 = fmaxf(mx0, __shfl_xor_sync(0xffffffffu, mx0, 1));
        mx0 = fmaxf(mx0, __shfl_xor_sync(0xffffffffu, mx0, 2));
        mx1 = fmaxf(mx1, __shfl_xor_sync(0xffffffffu, mx1, 1));
        mx1 = fmaxf(mx1, __shfl_xor_sync(0xffffffffu, mx1, 2));

        const float mn0 = fmaxf(m0, mx0);
        const float mn1 = fmaxf(m1, mx1);
        const float al0 = __expf(m0 - mn0);
        const float al1 = __expf(m1 - mn1);

        float s0 = 0.0f, s1 = 0.0f;
        #pragma unroll
        for (int t = 0; t < 8; t++) {
            sf[t][0] = __expf(sf[t][0] - mn0);
            sf[t][1] = __expf(sf[t][1] - mn0);
            sf[t][2] = __expf(sf[t][2] - mn1);
            sf[t][3] = __expf(sf[t][3] - mn1);
            s0 += sf[t][0] + sf[t][1];
            s1 += sf[t][2] + sf[t][3];
        }
        s0 += __shfl_xor_sync(0xffffffffu, s0, 1);
        s0 += __shfl_xor_sync(0xffffffffu, s0, 2);
        s1 += __shfl_xor_sync(0xffffffffu, s1, 1);
        s1 += __shfl_xor_sync(0xffffffffu, s1, 2);

        l0 = l0 * al0 + s0;  m0 = mn0;
        l1 = l1 * al1 + s1;  m1 = mn1;

        #pragma unroll
        for (int t = 0; t < 16; t++) {
            of[t][0] *= al0; of[t][1] *= al0;
            of[t][2] *= al1; of[t][3] *= al1;
        }

        #pragma unroll
        for (int t = 0; t < 8; t++) {
            const int wp = (t >> 1) * 8 + 2 * c4 + (t & 1);
            Ps[(mw + g)     * FLDP + wp] = f2h2(sf[t][0], sf[t][1]);
            Ps[(mw + g + 8) * FLDP + wp] = f2h2(sf[t][2], sf[t][3]);
        }
        __syncwarp();

        #pragma unroll
        for (int k = 0; k < 4; k++) {
            uint2 pa = *(const uint2*)&Ps[(mw + g)     * FLDP + k * 8 + 2 * c4];
            uint2 pb = *(const uint2*)&Ps[(mw + g + 8) * FLDP + k * 8 + 2 * c4];
            #pragma unroll
            for (int t = 0; t < 16; t++) {
                uint2 vb = *(const uint2*)&Vb[(k * 4 + c4) * FLDV + 2 * (t * 8 + g)];
                mma_f16(of[t], pa.x, pb.x, pa.y, pb.y, vb.x, vb.y);
            }
        }

        CP_WAIT0();
        __syncthreads();
    }

    const float inv0 = 1.0f / l0;
    const float inv1 = 1.0f / l1;
    const int r0f = q0 + mw + g;
    const int r1f = r0f + 8;
    const int grow0 = hb * 256 + (r0f >> 3);
    const int grow1 = hb * 256 + (r1f >> 3);
    const int cb0 = (r0f & 7) * 8;
    const int cb1 = (r1f & 7) * 8;
    #pragma unroll
    for (int t = 0; t < 16; t++) {
        const int sub = 2 * c4 + (t & 1);
        oh[grow0 * 512 + (cb0 + (t >> 1)) * 8 + sub] = f2h2(of[t][0] * inv0, of[t][1] * inv0);
        oh[grow1 * 512 + (cb1 + (t >> 1)) * 8 + sub] = f2h2(of[t][2] * inv1, of[t][3] * inv1);
    }
}

// ---------------------------------------------------------------------------
// Launch
// ---------------------------------------------------------------------------
extern "C" void kernel_launch(void* const* d_in, const int* in_sizes, int n_in,
                              void* d_out, int out_size)
{
    const float* x    = (const float*)d_in[0];  // [4,2048,128]
    const float* qkv  = (const float*)d_in[1];  // [128, 3072]
    const float* proj = (const float*)d_in[2];  // [1024, 128]
    float* out = (float*)d_out;                 // [4,2048,128]

    uint32_t *xh, *wh, *ph, *qh, *kh, *vp, *vh, *oh;
    cudaGetSymbolAddress((void**)&xh, g_xh);
    cudaGetSymbolAddress((void**)&wh, g_wh);
    cudaGetSymbolAddress((void**)&ph, g_ph);
    cudaGetSymbolAddress((void**)&qh, g_qh);
    cudaGetSymbolAddress((void**)&kh, g_kh);
    cudaGetSymbolAddress((void**)&vp, g_vp);
    cudaGetSymbolAddress((void**)&vh, g_vh);
    cudaGetSymbolAddress((void**)&oh, g_oh);

    convert_x_kernel<<<256, 256>>>(x, xh);
    convert_w_kernel<<<384, 256>>>(qkv, wh);
    convert_p_kernel<<<128, 256>>>(proj, ph);

    const int qkv_smem = (2 * 128 * 72 + 32 * 264) * (int)sizeof(uint32_t);  // 107,520
    cudaFuncSetAttribute(f16_gemm_qkv,
                         cudaFuncAttributeMaxDynamicSharedMemorySize, qkv_smem);
    f16_gemm_qkv<<<dim3(24, 16), 256, qkv_smem>>>(xh, wh, qh, kh, vp);

    convert_v_kernel<<<4096, 256>>>(vp, vh);

    const int flash_smem = FSMEMW * (int)sizeof(uint32_t);  // 109,568
    cudaFuncSetAttribute(flash_f16_kernel,
                         cudaFuncAttributeMaxDynamicSharedMemorySize, flash_smem);
    flash_f16_kernel<<<dim3(HEADS, SEQ / 128), 256, flash_smem>>>(qh, kh, vh, oh);

    const int proj_smem = (2 * 128 * 72 + 2 * 32 * 136) * (int)sizeof(uint32_t);  // 108,544
    cudaFuncSetAttribute(f16_gemm_proj,
                         cudaFuncAttributeMaxDynamicSharedMemorySize, proj_smem);
    f16_gemm_proj<<<dim3(2, 64), 256, proj_smem>>>(oh, ph, out);
}